// round 12
// baseline (speedup 1.0000x reference)
#include <cuda_runtime.h>
#include <cuda_bf16.h>
#include <cstdint>

// Problem constants
#define LNUM 2
#define SS   1024
#define MM   2048      // B*S tokens
#define NST  16        // SSM state dim
#define NCH  32        // scan chunks
#define TCH  32        // steps per chunk

#define FLAG_FLIP     2
#define FLAG_F32OUT   4
#define FLAG_PACKOUT  8

#define STAGES 3

// ---------------- scratch (static device memory; no allocation) ----------------
#define OFF_XP    0
#define OFF_XZ    (OFF_XP   + MM*512)
#define OFF_DBL   (OFF_XZ   + 2*MM*1024)
#define OFF_H0    (OFF_DBL  + 2*MM*48)
#define OFF_H1    (OFF_H0   + MM*512)
#define OFF_P     (OFF_H1   + MM*512)
#define OFF_HEND  (OFF_P    + 2*2*NCH*NST*512)
#define OFF_HINIT (OFF_HEND + 2*2*NCH*NST*512)
// packed activation planes (uint32 words in float slots): [hi][lo] per region
#define OFF_PKXN  (OFF_HINIT + 2*2*NCH*NST*512)
#define PKXN_W    (2*MM*128)
#define OFF_PKXC  (OFF_PKXN + 2*PKXN_W)
#define PKXC_W    (2*MM*256)
#define OFF_PKYG  (OFF_PKXC + 2*PKXC_W)
#define PKYG_W    (2*MM*256)
#define OFF_PKYC  (OFF_PKYG + 2*PKYG_W)
#define PKYC_W    (MM*256)
#define OFF_PKHO  (OFF_PKYC + 2*PKYC_W)
#define PKHO_W    (MM*256)
// packed bf16 hi/lo weights + input x
#define OFF_WPK   (OFF_PKHO + 2*PKHO_W)
#define WPK_IP    0
#define WPK_IN    (WPK_IP  + 262144)
#define WPK_OUT   (WPK_IN  + 524288)
#define WPK_OP    (WPK_OUT + 262144)
#define WPK_XP    (WPK_OP  + 262144)     // xprojW padded to 64 rows
#define WPK_XIN   (WPK_XP  + 65536)      // input x packed
#define WPK_HALF  (WPK_XIN + MM*256)
#define SCRATCH_TOTAL (OFF_WPK + 2*WPK_HALF)

__device__ float g_scratch[SCRATCH_TOTAL];

// ---------------- bf16 split helpers ----------------
__device__ __forceinline__ uint32_t cvt_pack_bf16(float up, float lo) {
    uint32_t r;
    asm("cvt.rn.bf16x2.f32 %0, %1, %2;" : "=r"(r) : "f"(up), "f"(lo));
    return r;
}
__device__ __forceinline__ void split_pair(float e0, float e1, uint32_t& h, uint32_t& l) {
    h = cvt_pack_bf16(e1, e0);
    float h0 = __uint_as_float(h << 16);
    float h1 = __uint_as_float(h & 0xffff0000u);
    l = cvt_pack_bf16(e1 - h1, e0 - h0);
}
__device__ __forceinline__ void split_scalar(float v, __nv_bfloat16& hb, __nv_bfloat16& lb) {
    hb = __float2bfloat16(v);
    lb = __float2bfloat16(v - __bfloat162float(hb));
}

__device__ __forceinline__ void mma_bf16(float4& c, const uint32_t a[4], const uint32_t b[2]) {
    asm volatile(
        "mma.sync.aligned.m16n8k16.row.col.f32.bf16.bf16.f32 "
        "{%0,%1,%2,%3}, {%4,%5,%6,%7}, {%8,%9}, {%0,%1,%2,%3};"
        : "+f"(c.x), "+f"(c.y), "+f"(c.z), "+f"(c.w)
        : "r"(a[0]), "r"(a[1]), "r"(a[2]), "r"(a[3]), "r"(b[0]), "r"(b[1]));
}

__device__ __forceinline__ void ldsm_x4(uint32_t& r0, uint32_t& r1, uint32_t& r2,
                                        uint32_t& r3, uint32_t addr) {
    asm volatile("ldmatrix.sync.aligned.m8n8.x4.shared.b16 {%0,%1,%2,%3}, [%4];"
                 : "=r"(r0), "=r"(r1), "=r"(r2), "=r"(r3) : "r"(addr));
}

__device__ __forceinline__ uint32_t smaddr(const void* p) {
    return static_cast<uint32_t>(__cvta_generic_to_shared(p));
}

__device__ __forceinline__ void cp16(uint32_t smem, const void* g) {
    asm volatile("cp.async.cg.shared.global [%0], [%1], 16;" :: "r"(smem), "l"(g) : "memory");
}

// ---------------- merged weight + x pre-pack ----------------
__global__ __launch_bounds__(256) void pack_all_kernel(
    const float* __restrict__ ipW, const float* __restrict__ inW,
    const float* __restrict__ outW, const float* __restrict__ opW,
    const float* __restrict__ xprojW, const float* __restrict__ xin,
    uint32_t* __restrict__ dstHi, uint32_t* __restrict__ dstLo)
{
    int i = blockIdx.x * 256 + threadIdx.x;
    if (i >= WPK_HALF) return;
    float2 v;
    if (i < WPK_XP) {
        const float* src;
        int local;
        if (i < WPK_IN)       { src = ipW;  local = i - WPK_IP; }
        else if (i < WPK_OUT) { src = inW;  local = i - WPK_IN; }
        else if (i < WPK_OP)  { src = outW; local = i - WPK_OUT; }
        else                  { src = opW;  local = i - WPK_OP; }
        v = *reinterpret_cast<const float2*>(&src[2 * local]);
    } else if (i < WPK_XIN) {
        int q = i - WPK_XP;                // [0, 65536)
        int ldir = q >> 14;                // 0..3
        int rem = q & 16383;
        int row = rem >> 8;                // 0..63
        int wp = rem & 255;
        if (row < 48)
            v = *reinterpret_cast<const float2*>(
                &xprojW[((size_t)ldir * 48 + row) * 512 + wp * 2]);
        else
            v = make_float2(0.f, 0.f);
    } else {
        int local = i - WPK_XIN;
        v = *reinterpret_cast<const float2*>(&xin[2 * local]);
    }
    uint32_t h, l;
    split_pair(v.x, v.y, h, l);
    dstHi[i] = h;
    dstLo[i] = l;
}

// ================= bf16-split mma.sync GEMM (BK=32, cp.async 3-stage) ==========
// Templated on BM (128 or 64). THREADS = 2*BM; warps in (BM/32)m x 2n grid.
template<int BM>
__global__ __launch_bounds__(BM * 2, (BM == 128) ? 3 : 4) void gemm_bf16_kernel(
    const uint32_t* __restrict__ Ahi, const uint32_t* __restrict__ Alo,
    int ldap, long long sAzp,
    const uint32_t* __restrict__ Whi, const uint32_t* __restrict__ Wlo,
    int ldwp, int sWzp,
    float* __restrict__ C, int ldc, long long sCz, int colOffPerZ,
    uint32_t* __restrict__ CpH, uint32_t* __restrict__ CpL, int ldcp,
    const float* __restrict__ bias, int sBiasZ,
    const float* __restrict__ resid, int ldres,
    int N_, int K_, int flags)
{
    constexpr int THREADS = BM * 2;
    constexpr int A_PLANE = BM * 64;
    constexpr int W_OFF   = 2 * A_PLANE;
    constexpr int STAGE   = 2 * A_PLANE + 8192;
    constexpr int AU      = 4;
    constexpr int WU      = 512 / THREADS;

    extern __shared__ unsigned char gsm[];
    const uint32_t sb = smaddr(gsm);

    const int tid = threadIdx.x;
    const int wid = tid >> 5, lane = tid & 31;
    const int wm = wid >> 1, wn = wid & 1;
    const int r = lane >> 2, c = lane & 3;

    const int z = blockIdx.z;
    const int m0 = blockIdx.y * BM, n0 = blockIdx.x * 64;
    const uint32_t* AhiZ = Ahi + (size_t)z * sAzp;
    const uint32_t* AloZ = Alo + (size_t)z * sAzp;
    const uint32_t* WhiZ = Whi + (size_t)z * sWzp;
    const uint32_t* WloZ = Wlo + (size_t)z * sWzp;

    float4 acc[2][4];
#pragma unroll
    for (int i = 0; i < 2; i++)
#pragma unroll
        for (int j = 0; j < 4; j++) acc[i][j] = make_float4(0.f, 0.f, 0.f, 0.f);

    const int NC = K_ >> 5;

    uint32_t aSo[AU]; const uint32_t* aSrc[AU]; size_t aG[AU];
#pragma unroll
    for (int i = 0; i < AU; i++) {
        int u = tid + i * THREADS;
        int plane = u / (4 * BM);
        int rem = u - plane * 4 * BM;
        int row = rem >> 2, q = rem & 3;
        aSo[i] = (uint32_t)(plane * A_PLANE + row * 64 + ((q ^ ((row >> 1) & 3)) * 16));
        aSrc[i] = plane ? AloZ : AhiZ;
        aG[i] = (size_t)(m0 + row) * ldap + q * 4;
    }
    uint32_t wSo[WU]; const uint32_t* wSrc[WU]; size_t wG[WU];
#pragma unroll
    for (int i = 0; i < WU; i++) {
        int u = tid + i * THREADS;
        int plane = u >> 8;
        int rem = u & 255;
        int row = rem >> 2, q = rem & 3;
        wSo[i] = (uint32_t)(W_OFF + plane * 4096 + row * 64 + ((q ^ ((row >> 1) & 3)) * 16));
        wSrc[i] = plane ? WloZ : WhiZ;
        wG[i] = (size_t)(n0 + row) * ldwp + q * 4;
    }

#pragma unroll
    for (int pc = 0; pc < STAGES - 1; pc++) {
        const uint32_t so = sb + pc * STAGE;
        const int cw = pc * 16;
#pragma unroll
        for (int i = 0; i < AU; i++) cp16(so + aSo[i], aSrc[i] + aG[i] + cw);
#pragma unroll
        for (int i = 0; i < WU; i++) cp16(so + wSo[i], wSrc[i] + wG[i] + cw);
        asm volatile("cp.async.commit_group;" ::: "memory");
    }

    const int mrow_in = ((lane >> 3) & 1) * 8 + (lane & 7);
    const int aUnitHi = lane >> 4;
    const int bUnitHi = (lane >> 3) & 1;
    const int bNtSel  = lane >> 4;
    const int bRowIn  = lane & 7;

    for (int cc = 0; cc < NC; cc++) {
        asm volatile("cp.async.wait_group 1;" ::: "memory");
        __syncthreads();

        if (cc + STAGES - 1 < NC) {
            const int nc2 = cc + STAGES - 1;
            const uint32_t so = sb + (nc2 % STAGES) * STAGE;
            const int cw = nc2 * 16;
#pragma unroll
            for (int i = 0; i < AU; i++) cp16(so + aSo[i], aSrc[i] + aG[i] + cw);
#pragma unroll
            for (int i = 0; i < WU; i++) cp16(so + wSo[i], wSrc[i] + wG[i] + cw);
        }
        asm volatile("cp.async.commit_group;" ::: "memory");

        const uint32_t a0b = sb + (cc % STAGES) * STAGE;
        const uint32_t a1b = a0b + A_PLANE;
        const uint32_t w0b = a0b + W_OFF;
        const uint32_t w1b = w0b + 4096;
#pragma unroll
        for (int s = 0; s < 2; s++) {
            uint32_t ah[2][4], al[2][4], bh[4][2], bl[4][2];
#pragma unroll
            for (int mt = 0; mt < 2; mt++) {
                int mrow = (wm * 2 + mt) * 16 + mrow_in;
                int q = (2 * s + aUnitHi) ^ ((mrow >> 1) & 3);
                uint32_t off = (uint32_t)(mrow * 64 + q * 16);
                ldsm_x4(ah[mt][0], ah[mt][1], ah[mt][2], ah[mt][3], a0b + off);
                ldsm_x4(al[mt][0], al[mt][1], al[mt][2], al[mt][3], a1b + off);
            }
#pragma unroll
            for (int p = 0; p < 2; p++) {
                int ntile = wn * 4 + p * 2 + bNtSel;
                int nrow = ntile * 8 + bRowIn;
                int q = (2 * s + bUnitHi) ^ ((nrow >> 1) & 3);
                uint32_t off = (uint32_t)(nrow * 64 + q * 16);
                ldsm_x4(bh[p * 2][0], bh[p * 2][1], bh[p * 2 + 1][0], bh[p * 2 + 1][1],
                        w0b + off);
                ldsm_x4(bl[p * 2][0], bl[p * 2][1], bl[p * 2 + 1][0], bl[p * 2 + 1][1],
                        w1b + off);
            }
#pragma unroll
            for (int mt = 0; mt < 2; mt++)
#pragma unroll
                for (int nt = 0; nt < 4; nt++) {
                    mma_bf16(acc[mt][nt], ah[mt], bh[nt]);
                    mma_bf16(acc[mt][nt], al[mt], bh[nt]);
                    mma_bf16(acc[mt][nt], ah[mt], bl[nt]);
                }
        }
    }

    const int coff = colOffPerZ * z;
#pragma unroll
    for (int mt = 0; mt < 2; mt++) {
        int mA = m0 + wm * 32 + mt * 16 + r;
        int mB = mA + 8;
        int rA = mA, rB = mB;
        if ((flags & FLAG_FLIP) && z == 1) {
            rA = (mA & ~(SS - 1)) + ((SS - 1) - (mA & (SS - 1)));
            rB = (mB & ~(SS - 1)) + ((SS - 1) - (mB & (SS - 1)));
        }
#pragma unroll
        for (int nt = 0; nt < 4; nt++) {
            int n = n0 + wn * 32 + nt * 8 + 2 * c;
            if (n >= N_) continue;
            float2 vA = make_float2(acc[mt][nt].x, acc[mt][nt].y);
            float2 vB = make_float2(acc[mt][nt].z, acc[mt][nt].w);
            if (bias) {
                float2 bv = *reinterpret_cast<const float2*>(&bias[z * sBiasZ + n]);
                vA.x += bv.x; vA.y += bv.y;
                vB.x += bv.x; vB.y += bv.y;
            }
            if (resid) {
                float2 qa = *reinterpret_cast<const float2*>(
                    &resid[(size_t)rA * ldres + coff + n]);
                float2 qb = *reinterpret_cast<const float2*>(
                    &resid[(size_t)rB * ldres + coff + n]);
                vA.x += qa.x; vA.y += qa.y;
                vB.x += qb.x; vB.y += qb.y;
            }
            if (flags & FLAG_F32OUT) {
                *reinterpret_cast<float2*>(
                    &C[(size_t)z * sCz + (size_t)rA * ldc + coff + n]) = vA;
                *reinterpret_cast<float2*>(
                    &C[(size_t)z * sCz + (size_t)rB * ldc + coff + n]) = vB;
            }
            if (flags & FLAG_PACKOUT) {
                uint32_t h, l;
                int wI = (coff + n) >> 1;
                split_pair(vA.x, vA.y, h, l);
                CpH[(size_t)rA * ldcp + wI] = h;
                CpL[(size_t)rA * ldcp + wI] = l;
                split_pair(vB.x, vB.y, h, l);
                CpH[(size_t)rB * ldcp + wI] = h;
                CpL[(size_t)rB * ldcp + wI] = l;
            }
        }
    }
}

// ---------------- LayerNorm, warp-per-row (Dvec=256, packed bf16 hi/lo out) ----------
__global__ __launch_bounds__(256) void ln256_kernel(
    const float* __restrict__ src,   // [MM][512]; z reads cols z*256.. (z=1 flipped S)
    const float* __restrict__ g, const float* __restrict__ bta,
    uint32_t* __restrict__ pH, uint32_t* __restrict__ pL)
{
    const int warp = threadIdx.x >> 5, lane = threadIdx.x & 31;
    const int m = blockIdx.x * 8 + warp;
    const int z = blockIdx.y;
    int srow = m;
    if (z == 1)
        srow = (m & ~(SS - 1)) + ((SS - 1) - (m & (SS - 1)));
    const float* sp = src + (size_t)srow * 512 + z * 256;

    float4 va = *reinterpret_cast<const float4*>(&sp[lane * 4]);
    float4 vb = *reinterpret_cast<const float4*>(&sp[128 + lane * 4]);
    float s1 = va.x + va.y + va.z + va.w + vb.x + vb.y + vb.z + vb.w;
    float s2 = va.x * va.x + va.y * va.y + va.z * va.z + va.w * va.w
             + vb.x * vb.x + vb.y * vb.y + vb.z * vb.z + vb.w * vb.w;
#pragma unroll
    for (int o = 16; o > 0; o >>= 1) {
        s1 += __shfl_xor_sync(0xffffffffu, s1, o);
        s2 += __shfl_xor_sync(0xffffffffu, s2, o);
    }
    const float mean = s1 * (1.f / 256.f);
    const float var  = s2 * (1.f / 256.f) - mean * mean;
    const float inv  = rsqrtf(var + 1e-5f);

    const float* gz = g + z * 256;
    const float* bz = bta + z * 256;
    float4 ga = *reinterpret_cast<const float4*>(&gz[lane * 4]);
    float4 gb = *reinterpret_cast<const float4*>(&gz[128 + lane * 4]);
    float4 ba = *reinterpret_cast<const float4*>(&bz[lane * 4]);
    float4 bb = *reinterpret_cast<const float4*>(&bz[128 + lane * 4]);

    float o0 = (va.x - mean) * inv * ga.x + ba.x;
    float o1 = (va.y - mean) * inv * ga.y + ba.y;
    float o2 = (va.z - mean) * inv * ga.z + ba.z;
    float o3 = (va.w - mean) * inv * ga.w + ba.w;
    float o4 = (vb.x - mean) * inv * gb.x + bb.x;
    float o5 = (vb.y - mean) * inv * gb.y + bb.y;
    float o6 = (vb.z - mean) * inv * gb.z + bb.z;
    float o7 = (vb.w - mean) * inv * gb.w + bb.w;

    uint32_t h0, l0, h1, l1, h2, l2, h3, l3;
    split_pair(o0, o1, h0, l0); split_pair(o2, o3, h1, l1);
    split_pair(o4, o5, h2, l2); split_pair(o6, o7, h3, l3);
    size_t wbase = ((size_t)z * MM + m) * 128;
    *reinterpret_cast<uint2*>(&pH[wbase + lane * 2])      = make_uint2(h0, h1);
    *reinterpret_cast<uint2*>(&pL[wbase + lane * 2])      = make_uint2(l0, l1);
    *reinterpret_cast<uint2*>(&pH[wbase + 64 + lane * 2]) = make_uint2(h2, h3);
    *reinterpret_cast<uint2*>(&pL[wbase + 64 + lane * 2]) = make_uint2(l2, l3);
}

// ---------------- LayerNorm, warp-per-row (Dvec=512, f32 out) ----------------
__global__ __launch_bounds__(256) void ln512_kernel(
    const float* __restrict__ src, const float* __restrict__ g,
    const float* __restrict__ bta, float* __restrict__ dst)
{
    const int warp = threadIdx.x >> 5, lane = threadIdx.x & 31;
    const int m = blockIdx.x * 8 + warp;
    const float* sp = src + (size_t)m * 512;

    float4 v[4];
    float s1 = 0.f, s2 = 0.f;
#pragma unroll
    for (int i = 0; i < 4; i++) {
        v[i] = *reinterpret_cast<const float4*>(&sp[i * 128 + lane * 4]);
        s1 += v[i].x + v[i].y + v[i].z + v[i].w;
        s2 += v[i].x * v[i].x + v[i].y * v[i].y + v[i].z * v[i].z + v[i].w * v[i].w;
    }
#pragma unroll
    for (int o = 16; o > 0; o >>= 1) {
        s1 += __shfl_xor_sync(0xffffffffu, s1, o);
        s2 += __shfl_xor_sync(0xffffffffu, s2, o);
    }
    const float mean = s1 * (1.f / 512.f);
    const float var  = s2 * (1.f / 512.f) - mean * mean;
    const float inv  = rsqrtf(var + 1e-5f);

    float* dp = dst + (size_t)m * 512;
#pragma unroll
    for (int i = 0; i < 4; i++) {
        float4 gv = *reinterpret_cast<const float4*>(&g[i * 128 + lane * 4]);
        float4 bv = *reinterpret_cast<const float4*>(&bta[i * 128 + lane * 4]);
        float4 o;
        o.x = (v[i].x - mean) * inv * gv.x + bv.x;
        o.y = (v[i].y - mean) * inv * gv.y + bv.y;
        o.z = (v[i].z - mean) * inv * gv.z + bv.z;
        o.w = (v[i].w - mean) * inv * gv.w + bv.w;
        *reinterpret_cast<float4*>(&dp[i * 128 + lane * 4]) = o;
    }
}

// ---------------- causal depthwise conv (K=4) + SiLU -> packed bf16 only ----------
__global__ __launch_bounds__(256) void conv_pack_kernel(
    const float* __restrict__ xz,   // [2][MM][1024], cols 0..511 are xc-raw
    const float* __restrict__ cW,   // [2][512][4]
    const float* __restrict__ cB,   // [2][512]
    __nv_bfloat16* __restrict__ xcH, __nv_bfloat16* __restrict__ xcL)
{
    int idx = blockIdx.x * 256 + threadIdx.x;      // < 2*MM*512 = 2^21
    int d   = idx & 511;
    int row = (idx >> 9) & (MM - 1);
    int z   = idx >> 20;
    int s   = row & (SS - 1);
    int bs0 = row - s;

    const float4 wv = *reinterpret_cast<const float4*>(&cW[((size_t)z * 512 + d) * 4]);
    const float w[4] = {wv.x, wv.y, wv.z, wv.w};
    float acc = cB[z * 512 + d];
    const float* xzz = xz + (size_t)z * MM * 1024;
#pragma unroll
    for (int k = 0; k < 4; k++) {
        int sp = s - 3 + k;
        if (sp >= 0) acc += w[k] * xzz[(size_t)(bs0 + sp) * 1024 + d];
    }
    float sig = 1.f / (1.f + __expf(-acc));
    float o = acc * sig;
    size_t oi = (size_t)z * MM * 512 + (size_t)row * 512 + d;
    __nv_bfloat16 hb, lb;
    split_scalar(o, hb, lb);
    xcH[oi] = hb; xcL[oi] = lb;
}

// ---------------- power-chain dA helper: dA[n] = q^(n+1) ----------------
__device__ __forceinline__ void qpowers(float q, float* dA) {
    float q2 = q * q, q3 = q2 * q, q4 = q2 * q2;
    float q8 = q4 * q4, q12 = q8 * q4;
    dA[0] = q;       dA[1] = q2;      dA[2] = q3;      dA[3] = q4;
    dA[4] = q4 * q;  dA[5] = q4 * q2; dA[6] = q4 * q3; dA[7] = q8;
    dA[8] = q8 * q;  dA[9] = q8 * q2; dA[10] = q8 * q3; dA[11] = q12;
    dA[12] = q12 * q; dA[13] = q12 * q2; dA[14] = q12 * q3; dA[15] = q8 * q8;
}

// inline conv+silu step helper (xv from sliding window)
__device__ __forceinline__ float conv_step(const float w[4], float bias,
                                           float w0, float w1, float w2, float cur) {
    float acc = bias;
    acc = fmaf(w[0], w0, acc);
    acc = fmaf(w[1], w1, acc);
    acc = fmaf(w[2], w2, acc);
    acc = fmaf(w[3], cur, acc);
    float sig = 1.f / (1.f + __expf(-acc));
    return acc * sig;
}

// ---------------- chunked SSM scan (conv + dt fused; fast exp path) ----------------
__global__ __launch_bounds__(256) void scan_phase1(
    const float* __restrict__ xzp,   // [2][MM][1024]
    const float* __restrict__ dblp,  // [2][MM][48]
    const float* __restrict__ A_log_l,
    const float* __restrict__ dtW_l, const float* __restrict__ dtB_l,
    const float* __restrict__ cW, const float* __restrict__ cB,
    float* __restrict__ P, float* __restrict__ hend)
{
    const int chunk = blockIdx.x >> 1;
    const int dg    = blockIdx.x & 1;
    const int b     = blockIdx.y, z = blockIdx.z;
    const int d     = dg * 256 + threadIdx.x;

    __shared__ float sIn[TCH][32];   // [t][0:16 dt-raw inputs, 16:32 B]
    const float* dbl_z = dblp + (size_t)z * MM * 48;
    const int base = b * SS + chunk * TCH;
    for (int i = threadIdx.x; i < TCH * 32; i += 256) {
        int t = i >> 5, n = i & 31;
        sIn[t][n] = dbl_z[(size_t)(base + t) * 48 + n];
    }
    __syncthreads();

    float a[NST], wdt[NST];
    const float* al = A_log_l + ((size_t)z * 512 + d) * NST;
    const float* wl = dtW_l + ((size_t)z * 512 + d) * NST;
    bool fast = true;
#pragma unroll
    for (int n = 0; n < NST; n++) {
        a[n] = -expf(al[n]); wdt[n] = wl[n];
        fast = fast && (fabsf(a[n] + (float)(n + 1)) <= 1e-3f * (n + 1));
    }
    const float bdt = dtB_l[z * 512 + d];

    const float4 cwv = *reinterpret_cast<const float4*>(&cW[((size_t)z * 512 + d) * 4]);
    const float cw[4] = {cwv.x, cwv.y, cwv.z, cwv.w};
    const float cb = cB[z * 512 + d];

    const float* xzz = xzp + (size_t)z * MM * 1024;
    float win0 = 0.f, win1 = 0.f, win2 = 0.f;
    if (chunk > 0) {
        win0 = xzz[(size_t)(base - 3) * 1024 + d];
        win1 = xzz[(size_t)(base - 2) * 1024 + d];
        win2 = xzz[(size_t)(base - 1) * 1024 + d];
    }

    float h[NST], Pr[NST];
#pragma unroll
    for (int n = 0; n < NST; n++) { h[n] = 0.f; Pr[n] = 1.f; }

    for (int t = 0; t < TCH; t++) {
        int row = base + t;
        float cur = xzz[(size_t)row * 1024 + d];
        float xv = conv_step(cw, cb, win0, win1, win2, cur);
        win0 = win1; win1 = win2; win2 = cur;

        float draw = bdt;
#pragma unroll
        for (int n = 0; n < NST; n++) draw = fmaf(wdt[n], sIn[t][n], draw);
        float dtv = (draw > 20.f) ? draw : log1pf(__expf(draw));
        float dx  = dtv * xv;
        if (fast) {
            float dA[NST];
            qpowers(__expf(-dtv), dA);
#pragma unroll
            for (int n = 0; n < NST; n++) {
                h[n]  = fmaf(dA[n], h[n], dx * sIn[t][16 + n]);
                Pr[n] *= dA[n];
            }
        } else {
#pragma unroll
            for (int n = 0; n < NST; n++) {
                float dA = __expf(dtv * a[n]);
                h[n]  = fmaf(dA, h[n], dx * sIn[t][16 + n]);
                Pr[n] *= dA;
            }
        }
    }
    size_t ob = ((((size_t)z * 2 + b) * NCH + chunk) * NST) * 512 + d;
#pragma unroll
    for (int n = 0; n < NST; n++) {
        P[ob + (size_t)n * 512]    = Pr[n];
        hend[ob + (size_t)n * 512] = h[n];
    }
}

__global__ __launch_bounds__(256) void scan_phase2(
    const float* __restrict__ P, const float* __restrict__ hend,
    float* __restrict__ hinit)
{
    int idx = blockIdx.x * 256 + threadIdx.x;   // 0..32767
    int d = idx & 511;
    int n = (idx >> 9) & 15;
    int b = (idx >> 13) & 1;
    int z = idx >> 14;
    size_t base = ((((size_t)z * 2 + b) * NCH) * NST + n) * 512 + d;
    const size_t cs = (size_t)NST * 512;

    float Pv[NCH], He[NCH];
#pragma unroll
    for (int c = 0; c < NCH; c++) {
        Pv[c] = P[base + (size_t)c * cs];
        He[c] = hend[base + (size_t)c * cs];
    }
    float h = 0.f;
#pragma unroll
    for (int c = 0; c < NCH; c++) {
        hinit[base + (size_t)c * cs] = h;
        h = fmaf(Pv[c], h, He[c]);
    }
}

__global__ __launch_bounds__(256) void scan_phase3(
    const float* __restrict__ xzp, const float* __restrict__ dblp,
    const float* __restrict__ A_log_l,
    const float* __restrict__ dtW_l, const float* __restrict__ dtB_l,
    const float* __restrict__ cW, const float* __restrict__ cB,
    const float* __restrict__ hinit, const float* __restrict__ Dp_l,
    __nv_bfloat16* __restrict__ ygH, __nv_bfloat16* __restrict__ ygL)
{
    const int chunk = blockIdx.x >> 1;
    const int dg    = blockIdx.x & 1;
    const int b     = blockIdx.y, z = blockIdx.z;
    const int d     = dg * 256 + threadIdx.x;

    __shared__ float sIn[TCH][48];   // [t][0:16 dt-in, 16:32 B, 32:48 C]
    const float* dbl_z = dblp + (size_t)z * MM * 48;
    const int base = b * SS + chunk * TCH;
    for (int i = threadIdx.x; i < TCH * 48; i += 256) {
        int t = i / 48, n = i % 48;
        sIn[t][n] = dbl_z[(size_t)(base + t) * 48 + n];
    }
    __syncthreads();

    float a[NST], wdt[NST];
    const float* al = A_log_l + ((size_t)z * 512 + d) * NST;
    const float* wl = dtW_l + ((size_t)z * 512 + d) * NST;
    bool fast = true;
#pragma unroll
    for (int n = 0; n < NST; n++) {
        a[n] = -expf(al[n]); wdt[n] = wl[n];
        fast = fast && (fabsf(a[n] + (float)(n + 1)) <= 1e-3f * (n + 1));
    }
    const float bdt = dtB_l[z * 512 + d];

    const float4 cwv = *reinterpret_cast<const float4*>(&cW[((size_t)z * 512 + d) * 4]);
    const float cw[4] = {cwv.x, cwv.y, cwv.z, cwv.w};
    const float cb = cB[z * 512 + d];

    const float* xzz = xzp + (size_t)z * MM * 1024;
    float win0 = 0.f, win1 = 0.f, win2 = 0.f;
    if (chunk > 0) {
        win0 = xzz[(size_t)(base - 3) * 1024 + d];
        win1 = xzz[(size_t)(base - 2) * 1024 + d];
        win2 = xzz[(size_t)(base - 1) * 1024 + d];
    }

    float h[NST];
    {
        size_t ob = ((((size_t)z * 2 + b) * NCH + chunk) * NST) * 512 + d;
#pragma unroll
        for (int n = 0; n < NST; n++) h[n] = hinit[ob + (size_t)n * 512];
    }
    const float Dv = Dp_l[z * 512 + d];

    for (int t = 0; t < TCH; t++) {
        int row = base + t;
        float cur = xzz[(size_t)row * 1024 + d];
        float xv = conv_step(cw, cb, win0, win1, win2, cur);
        win0 = win1; win1 = win2; win2 = cur;

        float draw = bdt;
#pragma unroll
        for (int n = 0; n < NST; n++) draw = fmaf(wdt[n], sIn[t][n], draw);
        float dtv = (draw > 20.f) ? draw : log1pf(__expf(draw));
        float dx  = dtv * xv;
        float y = 0.f;
        if (fast) {
            float dA[NST];
            qpowers(__expf(-dtv), dA);
#pragma unroll
            for (int n = 0; n < NST; n++) {
                h[n] = fmaf(dA[n], h[n], dx * sIn[t][16 + n]);
                y = fmaf(h[n], sIn[t][32 + n], y);
            }
        } else {
#pragma unroll
            for (int n = 0; n < NST; n++) {
                float dA = __expf(dtv * a[n]);
                h[n] = fmaf(dA, h[n], dx * sIn[t][16 + n]);
                y = fmaf(h[n], sIn[t][32 + n], y);
            }
        }
        float yfull = fmaf(xv, Dv, y);
        float zv = xzz[(size_t)row * 1024 + 512 + d];
        float sig = 1.f / (1.f + __expf(-zv));
        float o = yfull * zv * sig;
        size_t oi = (size_t)z * MM * 512 + (size_t)row * 512 + d;
        __nv_bfloat16 hb, lb;
        split_scalar(o, hb, lb);
        ygH[oi] = hb; ygL[oi] = lb;
    }
}

// ---------------- host orchestration ----------------
#define SMEM128 (STAGES * (2 * 128 * 64 + 8192))
#define SMEM64  (STAGES * (2 * 64 * 64 + 8192))

extern "C" void kernel_launch(void* const* d_in, const int* in_sizes, int n_in,
                              void* d_out, int out_size)
{
    const float* x      = (const float*)d_in[0];
    const float* ln_g   = (const float*)d_in[1];
    const float* ln_b   = (const float*)d_in[2];
    const float* inW    = (const float*)d_in[3];
    const float* convW  = (const float*)d_in[4];
    const float* convB  = (const float*)d_in[5];
    const float* xprojW = (const float*)d_in[6];
    const float* dtW    = (const float*)d_in[7];
    const float* dtB    = (const float*)d_in[8];
    const float* A_log  = (const float*)d_in[9];
    const float* Dp     = (const float*)d_in[10];
    const float* outW   = (const float*)d_in[11];
    const float* ipW    = (const float*)d_in[12];
    const float* ipB    = (const float*)d_in[13];
    const float* opW    = (const float*)d_in[14];
    const float* opB    = (const float*)d_in[15];
    const float* fln_g  = (const float*)d_in[16];
    const float* fln_b  = (const float*)d_in[17];

    static bool attr_set = false;
    if (!attr_set) {
        cudaFuncSetAttribute(gemm_bf16_kernel<128>,
                             cudaFuncAttributeMaxDynamicSharedMemorySize, SMEM128);
        cudaFuncSetAttribute(gemm_bf16_kernel<64>,
                             cudaFuncAttributeMaxDynamicSharedMemorySize, SMEM64);
        attr_set = true;
    }

    float* scratch = nullptr;
    cudaGetSymbolAddress((void**)&scratch, g_scratch);
    float* xp   = scratch + OFF_XP;
    float* xzb  = scratch + OFF_XZ;
    float* dbl  = scratch + OFF_DBL;
    float* hbuf[2] = { scratch + OFF_H0, scratch + OFF_H1 };
    float* Pb   = scratch + OFF_P;
    float* heb  = scratch + OFF_HEND;
    float* hib  = scratch + OFF_HINIT;

    uint32_t* xnH = (uint32_t*)(scratch + OFF_PKXN);
    uint32_t* xnL = xnH + PKXN_W;
    uint32_t* xcH = (uint32_t*)(scratch + OFF_PKXC);
    uint32_t* xcL = xcH + PKXC_W;
    uint32_t* ygH = (uint32_t*)(scratch + OFF_PKYG);
    uint32_t* ygL = ygH + PKYG_W;
    uint32_t* ycH = (uint32_t*)(scratch + OFF_PKYC);
    uint32_t* ycL = ycH + PKYC_W;
    uint32_t* hoH = (uint32_t*)(scratch + OFF_PKHO);
    uint32_t* hoL = hoH + PKHO_W;

    uint32_t* wpk = (uint32_t*)(scratch + OFF_WPK);
    uint32_t* wLo = wpk + WPK_HALF;
    uint32_t* ipH = wpk + WPK_IP;  uint32_t* ipL = wLo + WPK_IP;
    uint32_t* inH = wpk + WPK_IN;  uint32_t* inL = wLo + WPK_IN;
    uint32_t* otH = wpk + WPK_OUT; uint32_t* otL = wLo + WPK_OUT;
    uint32_t* opH = wpk + WPK_OP;  uint32_t* opL = wLo + WPK_OP;
    uint32_t* xpH = wpk + WPK_XP;  uint32_t* xpL = wLo + WPK_XP;
    uint32_t* xiH = wpk + WPK_XIN; uint32_t* xiL = wLo + WPK_XIN;

    // ---- pre-split all weights + input x ----
    pack_all_kernel<<<(WPK_HALF + 255) / 256, 256>>>(
        ipW, inW, outW, opW, xprojW, x, wpk, wLo);

    for (int l = 0; l < LNUM; l++) {
        const size_t l2 = (size_t)l * 2;
        const uint32_t* aH = (l == 0) ? xiH : hoH;
        const uint32_t* aL = (l == 0) ? xiL : hoL;

        // xp = hin @ ipW_l^T + ipB_l          (M=2048, N=512, K=512)  BM=64
        gemm_bf16_kernel<64><<<dim3(8, 32, 1), 128, SMEM64>>>(
            aH, aL, 256, 0,
            ipH + (size_t)l * 131072, ipL + (size_t)l * 131072, 256, 0,
            xp, 512, 0, 0, nullptr, nullptr, 0,
            ipB + l * 512, 0, nullptr, 0, 512, 512, FLAG_F32OUT);

        // per-dir LN over 256 (dir1 reads cols 256.. flipped S) -> packed xn
        ln256_kernel<<<dim3(MM / 8, 2), 256>>>(
            xp, ln_g + l2 * 256, ln_b + l2 * 256, xnH, xnL);

        // xz = xn @ inW^T                      (N=1024, K=256), both dirs  BM=128
        gemm_bf16_kernel<128><<<dim3(16, 16, 2), 256, SMEM128>>>(
            xnH, xnL, 128, (long long)MM * 128,
            inH + l2 * 131072, inL + l2 * 131072, 128, 131072,
            xzb, 1024, (long long)MM * 1024, 0, nullptr, nullptr, 0,
            nullptr, 0, nullptr, 0, 1024, 256, FLAG_F32OUT);

        // causal dwconv + silu -> packed xc only (for xproj GEMM)
        conv_pack_kernel<<<(2 * MM * 512) / 256, 256>>>(
            xzb, convW + l2 * 512 * 4, convB + l2 * 512,
            (__nv_bfloat16*)xcH, (__nv_bfloat16*)xcL);

        // dbl = xc @ xprojW^T                  (N=48 pad 64, K=512)  BM=64
        gemm_bf16_kernel<64><<<dim3(1, 32, 2), 128, SMEM64>>>(
            xcH, xcL, 256, (long long)MM * 256,
            xpH + l2 * 16384, xpL + l2 * 16384, 256, 16384,
            dbl, 48, (long long)MM * 48, 0, nullptr, nullptr, 0,
            nullptr, 0, nullptr, 0, 48, 512, FLAG_F32OUT);

        // chunked scan (conv + dt fused); phase3 emits packed yg
        scan_phase1<<<dim3(NCH * 2, 2, 2), 256>>>(
            xzb, dbl, A_log + l2 * 512 * NST,
            dtW + l2 * 512 * NST, dtB + l2 * 512,
            convW + l2 * 512 * 4, convB + l2 * 512, Pb, heb);
        scan_phase2<<<128, 256>>>(Pb, heb, hib);
        scan_phase3<<<dim3(NCH * 2, 2, 2), 256>>>(
            xzb, dbl, A_log + l2 * 512 * NST,
            dtW + l2 * 512 * NST, dtB + l2 * 512,
            convW + l2 * 512 * 4, convB + l2 * 512,
            hib, Dp + l2 * 512,
            (__nv_bfloat16*)ygH, (__nv_bfloat16*)ygL);

        // ycat[:, z*256..] = u + yg @ outW^T   (N=256, K=512), dir1 flip -> packed  BM=64
        gemm_bf16_kernel<64><<<dim3(4, 32, 2), 128, SMEM64>>>(
            ygH, ygL, 256, (long long)MM * 256,
            otH + l2 * 65536, otL + l2 * 65536, 256, 65536,
            nullptr, 512, 0, 256, ycH, ycL, 256,
            nullptr, 0, xp, 512, 256, 512, FLAG_PACKOUT | FLAG_FLIP);

        // h_next = ycat @ opW^T + opB          (N=512, K=512) -> f32 + packed  BM=64
        float* hout = hbuf[l & 1];
        gemm_bf16_kernel<64><<<dim3(8, 32, 1), 128, SMEM64>>>(
            ycH, ycL, 256, 0,
            opH + (size_t)l * 131072, opL + (size_t)l * 131072, 256, 0,
            hout, 512, 0, 0, hoH, hoL, 256,
            opB + l * 512, 0, nullptr, 0, 512, 512, FLAG_F32OUT | FLAG_PACKOUT);
    }

    // final LN over 512 -> d_out
    ln512_kernel<<<dim3(MM / 8, 1), 256>>>(
        hbuf[(LNUM - 1) & 1], fln_g, fln_b, (float*)d_out);
}

// round 15
// speedup vs baseline: 1.0736x; 1.0736x over previous
#include <cuda_runtime.h>
#include <cuda_bf16.h>
#include <cstdint>

// Problem constants
#define LNUM 2
#define SS   1024
#define MM   2048      // B*S tokens
#define NST  16        // SSM state dim
#define NCH  32        // scan chunks
#define TCH  32        // steps per chunk

#define FLAG_FLIP     2
#define FLAG_F32OUT   4
#define FLAG_PACKOUT  8

#define STAGES 3

// ---------------- scratch (static device memory; no allocation) ----------------
#define OFF_XP    0
#define OFF_XZ    (OFF_XP   + MM*512)
#define OFF_XC    (OFF_XZ   + 2*MM*1024)
#define OFF_DBL   (OFF_XC   + 2*MM*512)
#define OFF_H0    (OFF_DBL  + 2*MM*48)
#define OFF_H1    (OFF_H0   + MM*512)
#define OFF_P     (OFF_H1   + MM*512)
#define OFF_HEND  (OFF_P    + 2*2*NCH*NST*512)
#define OFF_HINIT (OFF_HEND + 2*2*NCH*NST*512)
// packed activation planes (uint32 words in float slots): [hi][lo] per region
#define OFF_PKXN  (OFF_HINIT + 2*2*NCH*NST*512)
#define PKXN_W    (2*MM*128)
#define OFF_PKXC  (OFF_PKXN + 2*PKXN_W)
#define PKXC_W    (2*MM*256)
#define OFF_PKYG  (OFF_PKXC + 2*PKXC_W)
#define PKYG_W    (2*MM*256)
#define OFF_PKYC  (OFF_PKYG + 2*PKYG_W)
#define PKYC_W    (MM*256)
#define OFF_PKHO  (OFF_PKYC + 2*PKYC_W)
#define PKHO_W    (MM*256)
// packed bf16 hi/lo weights + input x
#define OFF_WPK   (OFF_PKHO + 2*PKHO_W)
#define WPK_IP    0
#define WPK_IN    (WPK_IP  + 262144)
#define WPK_OUT   (WPK_IN  + 524288)
#define WPK_OP    (WPK_OUT + 262144)
#define WPK_XP    (WPK_OP  + 262144)     // xprojW padded to 64 rows
#define WPK_XIN   (WPK_XP  + 65536)      // input x packed
#define WPK_HALF  (WPK_XIN + MM*256)
#define SCRATCH_TOTAL (OFF_WPK + 2*WPK_HALF)

__device__ float g_scratch[SCRATCH_TOTAL];

// ---------------- bf16 split helpers ----------------
__device__ __forceinline__ uint32_t cvt_pack_bf16(float up, float lo) {
    uint32_t r;
    asm("cvt.rn.bf16x2.f32 %0, %1, %2;" : "=r"(r) : "f"(up), "f"(lo));
    return r;
}
__device__ __forceinline__ void split_pair(float e0, float e1, uint32_t& h, uint32_t& l) {
    h = cvt_pack_bf16(e1, e0);
    float h0 = __uint_as_float(h << 16);
    float h1 = __uint_as_float(h & 0xffff0000u);
    l = cvt_pack_bf16(e1 - h1, e0 - h0);
}
__device__ __forceinline__ void split_scalar(float v, __nv_bfloat16& hb, __nv_bfloat16& lb) {
    hb = __float2bfloat16(v);
    lb = __float2bfloat16(v - __bfloat162float(hb));
}

__device__ __forceinline__ void mma_bf16(float4& c, const uint32_t a[4], const uint32_t b[2]) {
    asm volatile(
        "mma.sync.aligned.m16n8k16.row.col.f32.bf16.bf16.f32 "
        "{%0,%1,%2,%3}, {%4,%5,%6,%7}, {%8,%9}, {%0,%1,%2,%3};"
        : "+f"(c.x), "+f"(c.y), "+f"(c.z), "+f"(c.w)
        : "r"(a[0]), "r"(a[1]), "r"(a[2]), "r"(a[3]), "r"(b[0]), "r"(b[1]));
}

__device__ __forceinline__ void ldsm_x4(uint32_t& r0, uint32_t& r1, uint32_t& r2,
                                        uint32_t& r3, uint32_t addr) {
    asm volatile("ldmatrix.sync.aligned.m8n8.x4.shared.b16 {%0,%1,%2,%3}, [%4];"
                 : "=r"(r0), "=r"(r1), "=r"(r2), "=r"(r3) : "r"(addr));
}

__device__ __forceinline__ uint32_t smaddr(const void* p) {
    return static_cast<uint32_t>(__cvta_generic_to_shared(p));
}

__device__ __forceinline__ void cp16(uint32_t smem, const void* g) {
    asm volatile("cp.async.cg.shared.global [%0], [%1], 16;" :: "r"(smem), "l"(g) : "memory");
}

// ---------------- merged weight + x pre-pack ----------------
__global__ __launch_bounds__(256) void pack_all_kernel(
    const float* __restrict__ ipW, const float* __restrict__ inW,
    const float* __restrict__ outW, const float* __restrict__ opW,
    const float* __restrict__ xprojW, const float* __restrict__ xin,
    uint32_t* __restrict__ dstHi, uint32_t* __restrict__ dstLo)
{
    int i = blockIdx.x * 256 + threadIdx.x;
    if (i >= WPK_HALF) return;
    float2 v;
    if (i < WPK_XP) {
        const float* src;
        int local;
        if (i < WPK_IN)       { src = ipW;  local = i - WPK_IP; }
        else if (i < WPK_OUT) { src = inW;  local = i - WPK_IN; }
        else if (i < WPK_OP)  { src = outW; local = i - WPK_OUT; }
        else                  { src = opW;  local = i - WPK_OP; }
        v = *reinterpret_cast<const float2*>(&src[2 * local]);
    } else if (i < WPK_XIN) {
        int q = i - WPK_XP;                // [0, 65536)
        int ldir = q >> 14;                // 0..3
        int rem = q & 16383;
        int row = rem >> 8;                // 0..63
        int wp = rem & 255;
        if (row < 48)
            v = *reinterpret_cast<const float2*>(
                &xprojW[((size_t)ldir * 48 + row) * 512 + wp * 2]);
        else
            v = make_float2(0.f, 0.f);
    } else {
        int local = i - WPK_XIN;
        v = *reinterpret_cast<const float2*>(&xin[2 * local]);
    }
    uint32_t h, l;
    split_pair(v.x, v.y, h, l);
    dstHi[i] = h;
    dstLo[i] = l;
}

// ================= bf16-split mma.sync GEMM (BK=32, cp.async 3-stage) ==========
// Templated on BM (128 or 64). THREADS = 2*BM; warps in (BM/32)m x 2n grid.
template<int BM>
__global__ __launch_bounds__(BM * 2, (BM == 128) ? 3 : 4) void gemm_bf16_kernel(
    const uint32_t* __restrict__ Ahi, const uint32_t* __restrict__ Alo,
    int ldap, long long sAzp,
    const uint32_t* __restrict__ Whi, const uint32_t* __restrict__ Wlo,
    int ldwp, int sWzp,
    float* __restrict__ C, int ldc, long long sCz, int colOffPerZ,
    uint32_t* __restrict__ CpH, uint32_t* __restrict__ CpL, int ldcp,
    const float* __restrict__ bias, int sBiasZ,
    const float* __restrict__ resid, int ldres,
    int N_, int K_, int flags)
{
    constexpr int THREADS = BM * 2;
    constexpr int A_PLANE = BM * 64;
    constexpr int W_OFF   = 2 * A_PLANE;
    constexpr int STAGE   = 2 * A_PLANE + 8192;
    constexpr int AU      = 4;
    constexpr int WU      = 512 / THREADS;

    extern __shared__ unsigned char gsm[];
    const uint32_t sb = smaddr(gsm);

    const int tid = threadIdx.x;
    const int wid = tid >> 5, lane = tid & 31;
    const int wm = wid >> 1, wn = wid & 1;
    const int r = lane >> 2, c = lane & 3;

    const int z = blockIdx.z;
    const int m0 = blockIdx.y * BM, n0 = blockIdx.x * 64;
    const uint32_t* AhiZ = Ahi + (size_t)z * sAzp;
    const uint32_t* AloZ = Alo + (size_t)z * sAzp;
    const uint32_t* WhiZ = Whi + (size_t)z * sWzp;
    const uint32_t* WloZ = Wlo + (size_t)z * sWzp;

    float4 acc[2][4];
#pragma unroll
    for (int i = 0; i < 2; i++)
#pragma unroll
        for (int j = 0; j < 4; j++) acc[i][j] = make_float4(0.f, 0.f, 0.f, 0.f);

    const int NC = K_ >> 5;

    uint32_t aSo[AU]; const uint32_t* aSrc[AU]; size_t aG[AU];
#pragma unroll
    for (int i = 0; i < AU; i++) {
        int u = tid + i * THREADS;
        int plane = u / (4 * BM);
        int rem = u - plane * 4 * BM;
        int row = rem >> 2, q = rem & 3;
        aSo[i] = (uint32_t)(plane * A_PLANE + row * 64 + ((q ^ ((row >> 1) & 3)) * 16));
        aSrc[i] = plane ? AloZ : AhiZ;
        aG[i] = (size_t)(m0 + row) * ldap + q * 4;
    }
    uint32_t wSo[WU]; const uint32_t* wSrc[WU]; size_t wG[WU];
#pragma unroll
    for (int i = 0; i < WU; i++) {
        int u = tid + i * THREADS;
        int plane = u >> 8;
        int rem = u & 255;
        int row = rem >> 2, q = rem & 3;
        wSo[i] = (uint32_t)(W_OFF + plane * 4096 + row * 64 + ((q ^ ((row >> 1) & 3)) * 16));
        wSrc[i] = plane ? WloZ : WhiZ;
        wG[i] = (size_t)(n0 + row) * ldwp + q * 4;
    }

#pragma unroll
    for (int pc = 0; pc < STAGES - 1; pc++) {
        const uint32_t so = sb + pc * STAGE;
        const int cw = pc * 16;
#pragma unroll
        for (int i = 0; i < AU; i++) cp16(so + aSo[i], aSrc[i] + aG[i] + cw);
#pragma unroll
        for (int i = 0; i < WU; i++) cp16(so + wSo[i], wSrc[i] + wG[i] + cw);
        asm volatile("cp.async.commit_group;" ::: "memory");
    }

    const int mrow_in = ((lane >> 3) & 1) * 8 + (lane & 7);
    const int aUnitHi = lane >> 4;
    const int bUnitHi = (lane >> 3) & 1;
    const int bNtSel  = lane >> 4;
    const int bRowIn  = lane & 7;

    for (int cc = 0; cc < NC; cc++) {
        asm volatile("cp.async.wait_group 1;" ::: "memory");
        __syncthreads();

        if (cc + STAGES - 1 < NC) {
            const int nc2 = cc + STAGES - 1;
            const uint32_t so = sb + (nc2 % STAGES) * STAGE;
            const int cw = nc2 * 16;
#pragma unroll
            for (int i = 0; i < AU; i++) cp16(so + aSo[i], aSrc[i] + aG[i] + cw);
#pragma unroll
            for (int i = 0; i < WU; i++) cp16(so + wSo[i], wSrc[i] + wG[i] + cw);
        }
        asm volatile("cp.async.commit_group;" ::: "memory");

        const uint32_t a0b = sb + (cc % STAGES) * STAGE;
        const uint32_t a1b = a0b + A_PLANE;
        const uint32_t w0b = a0b + W_OFF;
        const uint32_t w1b = w0b + 4096;
#pragma unroll
        for (int s = 0; s < 2; s++) {
            uint32_t ah[2][4], al[2][4], bh[4][2], bl[4][2];
#pragma unroll
            for (int mt = 0; mt < 2; mt++) {
                int mrow = (wm * 2 + mt) * 16 + mrow_in;
                int q = (2 * s + aUnitHi) ^ ((mrow >> 1) & 3);
                uint32_t off = (uint32_t)(mrow * 64 + q * 16);
                ldsm_x4(ah[mt][0], ah[mt][1], ah[mt][2], ah[mt][3], a0b + off);
                ldsm_x4(al[mt][0], al[mt][1], al[mt][2], al[mt][3], a1b + off);
            }
#pragma unroll
            for (int p = 0; p < 2; p++) {
                int ntile = wn * 4 + p * 2 + bNtSel;
                int nrow = ntile * 8 + bRowIn;
                int q = (2 * s + bUnitHi) ^ ((nrow >> 1) & 3);
                uint32_t off = (uint32_t)(nrow * 64 + q * 16);
                ldsm_x4(bh[p * 2][0], bh[p * 2][1], bh[p * 2 + 1][0], bh[p * 2 + 1][1],
                        w0b + off);
                ldsm_x4(bl[p * 2][0], bl[p * 2][1], bl[p * 2 + 1][0], bl[p * 2 + 1][1],
                        w1b + off);
            }
#pragma unroll
            for (int mt = 0; mt < 2; mt++)
#pragma unroll
                for (int nt = 0; nt < 4; nt++) {
                    mma_bf16(acc[mt][nt], ah[mt], bh[nt]);
                    mma_bf16(acc[mt][nt], al[mt], bh[nt]);
                    mma_bf16(acc[mt][nt], ah[mt], bl[nt]);
                }
        }
    }

    const int coff = colOffPerZ * z;
#pragma unroll
    for (int mt = 0; mt < 2; mt++) {
        int mA = m0 + wm * 32 + mt * 16 + r;
        int mB = mA + 8;
        int rA = mA, rB = mB;
        if ((flags & FLAG_FLIP) && z == 1) {
            rA = (mA & ~(SS - 1)) + ((SS - 1) - (mA & (SS - 1)));
            rB = (mB & ~(SS - 1)) + ((SS - 1) - (mB & (SS - 1)));
        }
#pragma unroll
        for (int nt = 0; nt < 4; nt++) {
            int n = n0 + wn * 32 + nt * 8 + 2 * c;
            if (n >= N_) continue;
            float2 vA = make_float2(acc[mt][nt].x, acc[mt][nt].y);
            float2 vB = make_float2(acc[mt][nt].z, acc[mt][nt].w);
            if (bias) {
                float2 bv = *reinterpret_cast<const float2*>(&bias[z * sBiasZ + n]);
                vA.x += bv.x; vA.y += bv.y;
                vB.x += bv.x; vB.y += bv.y;
            }
            if (resid) {
                float2 qa = *reinterpret_cast<const float2*>(
                    &resid[(size_t)rA * ldres + coff + n]);
                float2 qb = *reinterpret_cast<const float2*>(
                    &resid[(size_t)rB * ldres + coff + n]);
                vA.x += qa.x; vA.y += qa.y;
                vB.x += qb.x; vB.y += qb.y;
            }
            if (flags & FLAG_F32OUT) {
                *reinterpret_cast<float2*>(
                    &C[(size_t)z * sCz + (size_t)rA * ldc + coff + n]) = vA;
                *reinterpret_cast<float2*>(
                    &C[(size_t)z * sCz + (size_t)rB * ldc + coff + n]) = vB;
            }
            if (flags & FLAG_PACKOUT) {
                uint32_t h, l;
                int wI = (coff + n) >> 1;
                split_pair(vA.x, vA.y, h, l);
                CpH[(size_t)rA * ldcp + wI] = h;
                CpL[(size_t)rA * ldcp + wI] = l;
                split_pair(vB.x, vB.y, h, l);
                CpH[(size_t)rB * ldcp + wI] = h;
                CpL[(size_t)rB * ldcp + wI] = l;
            }
        }
    }
}

// ---------------- LayerNorm, warp-per-row (Dvec=256, packed bf16 hi/lo out) ----------
__global__ __launch_bounds__(256) void ln256_kernel(
    const float* __restrict__ src,   // [MM][512]; z reads cols z*256.. (z=1 flipped S)
    const float* __restrict__ g, const float* __restrict__ bta,
    uint32_t* __restrict__ pH, uint32_t* __restrict__ pL)
{
    const int warp = threadIdx.x >> 5, lane = threadIdx.x & 31;
    const int m = blockIdx.x * 8 + warp;
    const int z = blockIdx.y;
    int srow = m;
    if (z == 1)
        srow = (m & ~(SS - 1)) + ((SS - 1) - (m & (SS - 1)));
    const float* sp = src + (size_t)srow * 512 + z * 256;

    float4 va = *reinterpret_cast<const float4*>(&sp[lane * 4]);
    float4 vb = *reinterpret_cast<const float4*>(&sp[128 + lane * 4]);
    float s1 = va.x + va.y + va.z + va.w + vb.x + vb.y + vb.z + vb.w;
    float s2 = va.x * va.x + va.y * va.y + va.z * va.z + va.w * va.w
             + vb.x * vb.x + vb.y * vb.y + vb.z * vb.z + vb.w * vb.w;
#pragma unroll
    for (int o = 16; o > 0; o >>= 1) {
        s1 += __shfl_xor_sync(0xffffffffu, s1, o);
        s2 += __shfl_xor_sync(0xffffffffu, s2, o);
    }
    const float mean = s1 * (1.f / 256.f);
    const float var  = s2 * (1.f / 256.f) - mean * mean;
    const float inv  = rsqrtf(var + 1e-5f);

    const float* gz = g + z * 256;
    const float* bz = bta + z * 256;
    float4 ga = *reinterpret_cast<const float4*>(&gz[lane * 4]);
    float4 gb = *reinterpret_cast<const float4*>(&gz[128 + lane * 4]);
    float4 ba = *reinterpret_cast<const float4*>(&bz[lane * 4]);
    float4 bb = *reinterpret_cast<const float4*>(&bz[128 + lane * 4]);

    float o0 = (va.x - mean) * inv * ga.x + ba.x;
    float o1 = (va.y - mean) * inv * ga.y + ba.y;
    float o2 = (va.z - mean) * inv * ga.z + ba.z;
    float o3 = (va.w - mean) * inv * ga.w + ba.w;
    float o4 = (vb.x - mean) * inv * gb.x + bb.x;
    float o5 = (vb.y - mean) * inv * gb.y + bb.y;
    float o6 = (vb.z - mean) * inv * gb.z + bb.z;
    float o7 = (vb.w - mean) * inv * gb.w + bb.w;

    uint32_t h0, l0, h1, l1, h2, l2, h3, l3;
    split_pair(o0, o1, h0, l0); split_pair(o2, o3, h1, l1);
    split_pair(o4, o5, h2, l2); split_pair(o6, o7, h3, l3);
    size_t wbase = ((size_t)z * MM + m) * 128;
    *reinterpret_cast<uint2*>(&pH[wbase + lane * 2])      = make_uint2(h0, h1);
    *reinterpret_cast<uint2*>(&pL[wbase + lane * 2])      = make_uint2(l0, l1);
    *reinterpret_cast<uint2*>(&pH[wbase + 64 + lane * 2]) = make_uint2(h2, h3);
    *reinterpret_cast<uint2*>(&pL[wbase + 64 + lane * 2]) = make_uint2(l2, l3);
}

// ---------------- LayerNorm, warp-per-row (Dvec=512, f32 out) ----------------
__global__ __launch_bounds__(256) void ln512_kernel(
    const float* __restrict__ src, const float* __restrict__ g,
    const float* __restrict__ bta, float* __restrict__ dst)
{
    const int warp = threadIdx.x >> 5, lane = threadIdx.x & 31;
    const int m = blockIdx.x * 8 + warp;
    const float* sp = src + (size_t)m * 512;

    float4 v[4];
    float s1 = 0.f, s2 = 0.f;
#pragma unroll
    for (int i = 0; i < 4; i++) {
        v[i] = *reinterpret_cast<const float4*>(&sp[i * 128 + lane * 4]);
        s1 += v[i].x + v[i].y + v[i].z + v[i].w;
        s2 += v[i].x * v[i].x + v[i].y * v[i].y + v[i].z * v[i].z + v[i].w * v[i].w;
    }
#pragma unroll
    for (int o = 16; o > 0; o >>= 1) {
        s1 += __shfl_xor_sync(0xffffffffu, s1, o);
        s2 += __shfl_xor_sync(0xffffffffu, s2, o);
    }
    const float mean = s1 * (1.f / 512.f);
    const float var  = s2 * (1.f / 512.f) - mean * mean;
    const float inv  = rsqrtf(var + 1e-5f);

    float* dp = dst + (size_t)m * 512;
#pragma unroll
    for (int i = 0; i < 4; i++) {
        float4 gv = *reinterpret_cast<const float4*>(&g[i * 128 + lane * 4]);
        float4 bv = *reinterpret_cast<const float4*>(&bta[i * 128 + lane * 4]);
        float4 o;
        o.x = (v[i].x - mean) * inv * gv.x + bv.x;
        o.y = (v[i].y - mean) * inv * gv.y + bv.y;
        o.z = (v[i].z - mean) * inv * gv.z + bv.z;
        o.w = (v[i].w - mean) * inv * gv.w + bv.w;
        *reinterpret_cast<float4*>(&dp[i * 128 + lane * 4]) = o;
    }
}

// ---------------- causal depthwise conv (K=4) + SiLU; writes f32 + packed split ----
__global__ __launch_bounds__(256) void conv_silu_kernel(
    const float* __restrict__ xz,   // [2][MM][1024], cols 0..511 are xc-raw
    const float* __restrict__ cW,   // [2][512][4]
    const float* __restrict__ cB,   // [2][512]
    float* __restrict__ xc,         // [2][MM][512] f32 (for scans)
    __nv_bfloat16* __restrict__ xcH, __nv_bfloat16* __restrict__ xcL)
{
    int idx = blockIdx.x * 256 + threadIdx.x;      // < 2*MM*512 = 2^21
    int d   = idx & 511;
    int row = (idx >> 9) & (MM - 1);
    int z   = idx >> 20;
    int s   = row & (SS - 1);
    int bs0 = row - s;

    const float4 wv = *reinterpret_cast<const float4*>(&cW[((size_t)z * 512 + d) * 4]);
    const float w[4] = {wv.x, wv.y, wv.z, wv.w};
    float acc = cB[z * 512 + d];
    const float* xzz = xz + (size_t)z * MM * 1024;
#pragma unroll
    for (int k = 0; k < 4; k++) {
        int sp = s - 3 + k;
        if (sp >= 0) acc += w[k] * xzz[(size_t)(bs0 + sp) * 1024 + d];
    }
    float sig = 1.f / (1.f + __expf(-acc));
    float o = acc * sig;
    size_t oi = (size_t)z * MM * 512 + (size_t)row * 512 + d;
    xc[oi] = o;
    __nv_bfloat16 hb, lb;
    split_scalar(o, hb, lb);
    xcH[oi] = hb; xcL[oi] = lb;
}

// ---------------- power-chain dA helper: dA[n] = q^(n+1) ----------------
__device__ __forceinline__ void qpowers(float q, float* dA) {
    float q2 = q * q, q3 = q2 * q, q4 = q2 * q2;
    float q8 = q4 * q4, q12 = q8 * q4;
    dA[0] = q;       dA[1] = q2;      dA[2] = q3;      dA[3] = q4;
    dA[4] = q4 * q;  dA[5] = q4 * q2; dA[6] = q4 * q3; dA[7] = q8;
    dA[8] = q8 * q;  dA[9] = q8 * q2; dA[10] = q8 * q3; dA[11] = q12;
    dA[12] = q12 * q; dA[13] = q12 * q2; dA[14] = q12 * q3; dA[15] = q8 * q8;
}

// ---------------- chunked SSM scan (dt fused; fast exp path) ----------------
__global__ __launch_bounds__(256) void scan_phase1(
    const float* __restrict__ xcp, const float* __restrict__ dblp,
    const float* __restrict__ A_log_l,
    const float* __restrict__ dtW_l, const float* __restrict__ dtB_l,
    float* __restrict__ P, float* __restrict__ hend)
{
    const int chunk = blockIdx.x >> 1;
    const int dg    = blockIdx.x & 1;
    const int b     = blockIdx.y, z = blockIdx.z;
    const int d     = dg * 256 + threadIdx.x;

    __shared__ float sIn[TCH][32];   // [t][0:16 dt-raw inputs, 16:32 B]
    const float* dbl_z = dblp + (size_t)z * MM * 48;
    const int base = b * SS + chunk * TCH;
    for (int i = threadIdx.x; i < TCH * 32; i += 256) {
        int t = i >> 5, n = i & 31;
        sIn[t][n] = dbl_z[(size_t)(base + t) * 48 + n];
    }
    __syncthreads();

    float a[NST], wdt[NST];
    const float* al = A_log_l + ((size_t)z * 512 + d) * NST;
    const float* wl = dtW_l + ((size_t)z * 512 + d) * NST;
    bool fast = true;
#pragma unroll
    for (int n = 0; n < NST; n++) {
        a[n] = -expf(al[n]); wdt[n] = wl[n];
        fast = fast && (fabsf(a[n] + (float)(n + 1)) <= 1e-3f * (n + 1));
    }
    const float bdt = dtB_l[z * 512 + d];

    float h[NST], Pr[NST];
#pragma unroll
    for (int n = 0; n < NST; n++) { h[n] = 0.f; Pr[n] = 1.f; }

    const float* xcz = xcp + (size_t)z * MM * 512;
    if (fast) {
        for (int t = 0; t < TCH; t++) {
            int row = base + t;
            float draw = bdt;
#pragma unroll
            for (int n = 0; n < NST; n++) draw = fmaf(wdt[n], sIn[t][n], draw);
            float dtv = (draw > 20.f) ? draw : log1pf(__expf(draw));
            float xv  = xcz[(size_t)row * 512 + d];
            float dx  = dtv * xv;
            float dA[NST];
            qpowers(__expf(-dtv), dA);
#pragma unroll
            for (int n = 0; n < NST; n++) {
                h[n]  = fmaf(dA[n], h[n], dx * sIn[t][16 + n]);
                Pr[n] *= dA[n];
            }
        }
    } else {
        for (int t = 0; t < TCH; t++) {
            int row = base + t;
            float draw = bdt;
#pragma unroll
            for (int n = 0; n < NST; n++) draw = fmaf(wdt[n], sIn[t][n], draw);
            float dtv = (draw > 20.f) ? draw : log1pf(__expf(draw));
            float xv  = xcz[(size_t)row * 512 + d];
            float dx  = dtv * xv;
#pragma unroll
            for (int n = 0; n < NST; n++) {
                float dA = __expf(dtv * a[n]);
                h[n]  = fmaf(dA, h[n], dx * sIn[t][16 + n]);
                Pr[n] *= dA;
            }
        }
    }
    size_t ob = ((((size_t)z * 2 + b) * NCH + chunk) * NST) * 512 + d;
#pragma unroll
    for (int n = 0; n < NST; n++) {
        P[ob + (size_t)n * 512]    = Pr[n];
        hend[ob + (size_t)n * 512] = h[n];
    }
}

__global__ __launch_bounds__(256) void scan_phase2(
    const float* __restrict__ P, const float* __restrict__ hend,
    float* __restrict__ hinit)
{
    int idx = blockIdx.x * 256 + threadIdx.x;   // 0..32767
    int d = idx & 511;
    int n = (idx >> 9) & 15;
    int b = (idx >> 13) & 1;
    int z = idx >> 14;
    size_t base = ((((size_t)z * 2 + b) * NCH) * NST + n) * 512 + d;
    const size_t cs = (size_t)NST * 512;

    float Pv[NCH], He[NCH];
#pragma unroll
    for (int c = 0; c < NCH; c++) {
        Pv[c] = P[base + (size_t)c * cs];
        He[c] = hend[base + (size_t)c * cs];
    }
    float h = 0.f;
#pragma unroll
    for (int c = 0; c < NCH; c++) {
        hinit[base + (size_t)c * cs] = h;
        h = fmaf(Pv[c], h, He[c]);
    }
}

__global__ __launch_bounds__(256) void scan_phase3(
    const float* __restrict__ xcp, const float* __restrict__ dblp,
    const float* __restrict__ A_log_l,
    const float* __restrict__ dtW_l, const float* __restrict__ dtB_l,
    const float* __restrict__ hinit,
    const float* __restrict__ xzp, const float* __restrict__ Dp_l,
    __nv_bfloat16* __restrict__ ygH, __nv_bfloat16* __restrict__ ygL)
{
    const int chunk = blockIdx.x >> 1;
    const int dg    = blockIdx.x & 1;
    const int b     = blockIdx.y, z = blockIdx.z;
    const int d     = dg * 256 + threadIdx.x;

    __shared__ float sIn[TCH][48];   // [t][0:16 dt-in, 16:32 B, 32:48 C]
    const float* dbl_z = dblp + (size_t)z * MM * 48;
    const int base = b * SS + chunk * TCH;
    for (int i = threadIdx.x; i < TCH * 48; i += 256) {
        int t = i / 48, n = i % 48;
        sIn[t][n] = dbl_z[(size_t)(base + t) * 48 + n];
    }
    __syncthreads();

    float a[NST], wdt[NST];
    const float* al = A_log_l + ((size_t)z * 512 + d) * NST;
    const float* wl = dtW_l + ((size_t)z * 512 + d) * NST;
    bool fast = true;
#pragma unroll
    for (int n = 0; n < NST; n++) {
        a[n] = -expf(al[n]); wdt[n] = wl[n];
        fast = fast && (fabsf(a[n] + (float)(n + 1)) <= 1e-3f * (n + 1));
    }
    const float bdt = dtB_l[z * 512 + d];

    float h[NST];
    {
        size_t ob = ((((size_t)z * 2 + b) * NCH + chunk) * NST) * 512 + d;
#pragma unroll
        for (int n = 0; n < NST; n++) h[n] = hinit[ob + (size_t)n * 512];
    }
    const float Dv = Dp_l[z * 512 + d];
    const float* xcz = xcp + (size_t)z * MM * 512;
    const float* xzz = xzp + (size_t)z * MM * 1024;

    for (int t = 0; t < TCH; t++) {
        int row = base + t;
        float draw = bdt;
#pragma unroll
        for (int n = 0; n < NST; n++) draw = fmaf(wdt[n], sIn[t][n], draw);
        float dtv = (draw > 20.f) ? draw : log1pf(__expf(draw));
        float xv  = xcz[(size_t)row * 512 + d];
        float dx  = dtv * xv;
        float y = 0.f;
        if (fast) {
            float dA[NST];
            qpowers(__expf(-dtv), dA);
#pragma unroll
            for (int n = 0; n < NST; n++) {
                h[n] = fmaf(dA[n], h[n], dx * sIn[t][16 + n]);
                y = fmaf(h[n], sIn[t][32 + n], y);
            }
        } else {
#pragma unroll
            for (int n = 0; n < NST; n++) {
                float dA = __expf(dtv * a[n]);
                h[n] = fmaf(dA, h[n], dx * sIn[t][16 + n]);
                y = fmaf(h[n], sIn[t][32 + n], y);
            }
        }
        float yfull = fmaf(xv, Dv, y);
        float zv = xzz[(size_t)row * 1024 + 512 + d];
        float sig = 1.f / (1.f + __expf(-zv));
        float o = yfull * zv * sig;
        size_t oi = (size_t)z * MM * 512 + (size_t)row * 512 + d;
        __nv_bfloat16 hb, lb;
        split_scalar(o, hb, lb);
        ygH[oi] = hb; ygL[oi] = lb;
    }
}

// ---------------- host orchestration ----------------
#define SMEM128 (STAGES * (2 * 128 * 64 + 8192))
#define SMEM64  (STAGES * (2 * 64 * 64 + 8192))

extern "C" void kernel_launch(void* const* d_in, const int* in_sizes, int n_in,
                              void* d_out, int out_size)
{
    const float* x      = (const float*)d_in[0];
    const float* ln_g   = (const float*)d_in[1];
    const float* ln_b   = (const float*)d_in[2];
    const float* inW    = (const float*)d_in[3];
    const float* convW  = (const float*)d_in[4];
    const float* convB  = (const float*)d_in[5];
    const float* xprojW = (const float*)d_in[6];
    const float* dtW    = (const float*)d_in[7];
    const float* dtB    = (const float*)d_in[8];
    const float* A_log  = (const float*)d_in[9];
    const float* Dp     = (const float*)d_in[10];
    const float* outW   = (const float*)d_in[11];
    const float* ipW    = (const float*)d_in[12];
    const float* ipB    = (const float*)d_in[13];
    const float* opW    = (const float*)d_in[14];
    const float* opB    = (const float*)d_in[15];
    const float* fln_g  = (const float*)d_in[16];
    const float* fln_b  = (const float*)d_in[17];

    static bool attr_set = false;
    if (!attr_set) {
        cudaFuncSetAttribute(gemm_bf16_kernel<128>,
                             cudaFuncAttributeMaxDynamicSharedMemorySize, SMEM128);
        cudaFuncSetAttribute(gemm_bf16_kernel<64>,
                             cudaFuncAttributeMaxDynamicSharedMemorySize, SMEM64);
        attr_set = true;
    }

    float* scratch = nullptr;
    cudaGetSymbolAddress((void**)&scratch, g_scratch);
    float* xp   = scratch + OFF_XP;
    float* xzb  = scratch + OFF_XZ;
    float* xc   = scratch + OFF_XC;
    float* dbl  = scratch + OFF_DBL;
    float* hbuf[2] = { scratch + OFF_H0, scratch + OFF_H1 };
    float* Pb   = scratch + OFF_P;
    float* heb  = scratch + OFF_HEND;
    float* hib  = scratch + OFF_HINIT;

    uint32_t* xnH = (uint32_t*)(scratch + OFF_PKXN);
    uint32_t* xnL = xnH + PKXN_W;
    uint32_t* xcH = (uint32_t*)(scratch + OFF_PKXC);
    uint32_t* xcL = xcH + PKXC_W;
    uint32_t* ygH = (uint32_t*)(scratch + OFF_PKYG);
    uint32_t* ygL = ygH + PKYG_W;
    uint32_t* ycH = (uint32_t*)(scratch + OFF_PKYC);
    uint32_t* ycL = ycH + PKYC_W;
    uint32_t* hoH = (uint32_t*)(scratch + OFF_PKHO);
    uint32_t* hoL = hoH + PKHO_W;

    uint32_t* wpk = (uint32_t*)(scratch + OFF_WPK);
    uint32_t* wLo = wpk + WPK_HALF;
    uint32_t* ipH = wpk + WPK_IP;  uint32_t* ipL = wLo + WPK_IP;
    uint32_t* inH = wpk + WPK_IN;  uint32_t* inL = wLo + WPK_IN;
    uint32_t* otH = wpk + WPK_OUT; uint32_t* otL = wLo + WPK_OUT;
    uint32_t* opH = wpk + WPK_OP;  uint32_t* opL = wLo + WPK_OP;
    uint32_t* xpH = wpk + WPK_XP;  uint32_t* xpL = wLo + WPK_XP;
    uint32_t* xiH = wpk + WPK_XIN; uint32_t* xiL = wLo + WPK_XIN;

    // ---- pre-split all weights + input x ----
    pack_all_kernel<<<(WPK_HALF + 255) / 256, 256>>>(
        ipW, inW, outW, opW, xprojW, x, wpk, wLo);

    for (int l = 0; l < LNUM; l++) {
        const size_t l2 = (size_t)l * 2;
        const uint32_t* aH = (l == 0) ? xiH : hoH;
        const uint32_t* aL = (l == 0) ? xiL : hoL;

        // xp = hin @ ipW_l^T + ipB_l          (M=2048, N=512, K=512)  BM=64
        gemm_bf16_kernel<64><<<dim3(8, 32, 1), 128, SMEM64>>>(
            aH, aL, 256, 0,
            ipH + (size_t)l * 131072, ipL + (size_t)l * 131072, 256, 0,
            xp, 512, 0, 0, nullptr, nullptr, 0,
            ipB + l * 512, 0, nullptr, 0, 512, 512, FLAG_F32OUT);

        // per-dir LN over 256 (dir1 reads cols 256.. flipped S) -> packed xn
        ln256_kernel<<<dim3(MM / 8, 2), 256>>>(
            xp, ln_g + l2 * 256, ln_b + l2 * 256, xnH, xnL);

        // xz = xn @ inW^T                      (N=1024, K=256), both dirs  BM=64
        gemm_bf16_kernel<64><<<dim3(16, 32, 2), 128, SMEM64>>>(
            xnH, xnL, 128, (long long)MM * 128,
            inH + l2 * 131072, inL + l2 * 131072, 128, 131072,
            xzb, 1024, (long long)MM * 1024, 0, nullptr, nullptr, 0,
            nullptr, 0, nullptr, 0, 1024, 256, FLAG_F32OUT);

        // causal dwconv + silu -> f32 xc + packed xc
        conv_silu_kernel<<<(2 * MM * 512) / 256, 256>>>(
            xzb, convW + l2 * 512 * 4, convB + l2 * 512, xc,
            (__nv_bfloat16*)xcH, (__nv_bfloat16*)xcL);

        // dbl = xc @ xprojW^T                  (N=48 pad 64, K=512)  BM=64
        gemm_bf16_kernel<64><<<dim3(1, 32, 2), 128, SMEM64>>>(
            xcH, xcL, 256, (long long)MM * 256,
            xpH + l2 * 16384, xpL + l2 * 16384, 256, 16384,
            dbl, 48, (long long)MM * 48, 0, nullptr, nullptr, 0,
            nullptr, 0, nullptr, 0, 48, 512, FLAG_F32OUT);

        // chunked scan (dt fused); phase3 emits packed yg
        scan_phase1<<<dim3(NCH * 2, 2, 2), 256>>>(
            xc, dbl, A_log + l2 * 512 * NST,
            dtW + l2 * 512 * NST, dtB + l2 * 512, Pb, heb);
        scan_phase2<<<128, 256>>>(Pb, heb, hib);
        scan_phase3<<<dim3(NCH * 2, 2, 2), 256>>>(
            xc, dbl, A_log + l2 * 512 * NST,
            dtW + l2 * 512 * NST, dtB + l2 * 512,
            hib, xzb, Dp + l2 * 512,
            (__nv_bfloat16*)ygH, (__nv_bfloat16*)ygL);

        // ycat[:, z*256..] = u + yg @ outW^T   (N=256, K=512), dir1 flip -> packed  BM=64
        gemm_bf16_kernel<64><<<dim3(4, 32, 2), 128, SMEM64>>>(
            ygH, ygL, 256, (long long)MM * 256,
            otH + l2 * 65536, otL + l2 * 65536, 256, 65536,
            nullptr, 512, 0, 256, ycH, ycL, 256,
            nullptr, 0, xp, 512, 256, 512, FLAG_PACKOUT | FLAG_FLIP);

        // h_next = ycat @ opW^T + opB          (N=512, K=512) -> f32 + packed  BM=64
        float* hout = hbuf[l & 1];
        gemm_bf16_kernel<64><<<dim3(8, 32, 1), 128, SMEM64>>>(
            ycH, ycL, 256, 0,
            opH + (size_t)l * 131072, opL + (size_t)l * 131072, 256, 0,
            hout, 512, 0, 0, hoH, hoL, 256,
            opB + l * 512, 0, nullptr, 0, 512, 512, FLAG_F32OUT | FLAG_PACKOUT);
    }

    // final LN over 512 -> d_out
    ln512_kernel<<<dim3(MM / 8, 1), 256>>>(
        hbuf[(LNUM - 1) & 1], fln_g, fln_b, (float*)d_out);
}

// round 16
// speedup vs baseline: 1.1145x; 1.0381x over previous
#include <cuda_runtime.h>
#include <cuda_bf16.h>
#include <cstdint>

// Problem constants
#define LNUM 2
#define SS   1024
#define MM   2048      // B*S tokens
#define NST  16        // SSM state dim
#define NCH  32        // scan chunks
#define TCH  32        // steps per chunk

#define FLAG_FLIP     2
#define FLAG_F32OUT   4
#define FLAG_PACKOUT  8

#define STAGES 3

// ---------------- scratch (static device memory; no allocation) ----------------
#define OFF_XP    0
#define OFF_XZ    (OFF_XP   + MM*512)
#define OFF_XC    (OFF_XZ   + 2*MM*1024)
#define OFF_DBL   (OFF_XC   + 2*MM*512)
#define OFF_H0    (OFF_DBL  + 2*MM*48)
#define OFF_H1    (OFF_H0   + MM*512)
#define OFF_P     (OFF_H1   + MM*512)
#define OFF_HEND  (OFF_P    + 2*2*NCH*NST*512)
#define OFF_HINIT (OFF_HEND + 2*2*NCH*NST*512)
// packed activation planes (uint32 words in float slots): [hi][lo] per region
#define OFF_PKXN  (OFF_HINIT + 2*2*NCH*NST*512)
#define PKXN_W    (2*MM*128)
#define OFF_PKXC  (OFF_PKXN + 2*PKXN_W)
#define PKXC_W    (2*MM*256)
#define OFF_PKYG  (OFF_PKXC + 2*PKXC_W)
#define PKYG_W    (2*MM*256)
#define OFF_PKYC  (OFF_PKYG + 2*PKYG_W)
#define PKYC_W    (MM*256)
#define OFF_PKHO  (OFF_PKYC + 2*PKYC_W)
#define PKHO_W    (MM*256)
// packed bf16 hi/lo weights + input x
#define OFF_WPK   (OFF_PKHO + 2*PKHO_W)
#define WPK_IP    0
#define WPK_IN    (WPK_IP  + 262144)
#define WPK_OUT   (WPK_IN  + 524288)
#define WPK_OP    (WPK_OUT + 262144)
#define WPK_XP    (WPK_OP  + 262144)     // xprojW padded to 64 rows
#define WPK_XIN   (WPK_XP  + 65536)      // input x packed
#define WPK_HALF  (WPK_XIN + MM*256)
#define SCRATCH_TOTAL (OFF_WPK + 2*WPK_HALF)

__device__ float g_scratch[SCRATCH_TOTAL];

// ---------------- bf16 split helpers ----------------
__device__ __forceinline__ uint32_t cvt_pack_bf16(float up, float lo) {
    uint32_t r;
    asm("cvt.rn.bf16x2.f32 %0, %1, %2;" : "=r"(r) : "f"(up), "f"(lo));
    return r;
}
__device__ __forceinline__ void split_pair(float e0, float e1, uint32_t& h, uint32_t& l) {
    h = cvt_pack_bf16(e1, e0);
    float h0 = __uint_as_float(h << 16);
    float h1 = __uint_as_float(h & 0xffff0000u);
    l = cvt_pack_bf16(e1 - h1, e0 - h0);
}
__device__ __forceinline__ void split_scalar(float v, __nv_bfloat16& hb, __nv_bfloat16& lb) {
    hb = __float2bfloat16(v);
    lb = __float2bfloat16(v - __bfloat162float(hb));
}

// ---------------- f32x2 packed math ----------------
#define PACKF2(d, lo, hi) asm("mov.b64 %0, {%1, %2};" : "=l"(d) : "f"(lo), "f"(hi))
#define PACK_DUP(dst, s)  asm("mov.b64 %0, {%1, %1};" : "=l"(dst) : "f"(s))
#define UNPACKF2(lo, hi, v) asm("mov.b64 {%0, %1}, %2;" : "=f"(lo), "=f"(hi) : "l"(v))
#define MUL2(d, a, b)  asm("mul.rn.f32x2 %0, %1, %2;" : "=l"(d) : "l"(a), "l"(b))
#define FMA2(acc, a, b) asm("fma.rn.f32x2 %0, %1, %2, %0;" : "+l"(acc) : "l"(a), "l"(b))
#define FMA2_3(d, a, b, c) \
    asm("fma.rn.f32x2 %0, %1, %2, %3;" : "=l"(d) : "l"(a), "l"(b), "l"(c))

__device__ __forceinline__ void mma_bf16(float4& c, const uint32_t a[4], const uint32_t b[2]) {
    asm volatile(
        "mma.sync.aligned.m16n8k16.row.col.f32.bf16.bf16.f32 "
        "{%0,%1,%2,%3}, {%4,%5,%6,%7}, {%8,%9}, {%0,%1,%2,%3};"
        : "+f"(c.x), "+f"(c.y), "+f"(c.z), "+f"(c.w)
        : "r"(a[0]), "r"(a[1]), "r"(a[2]), "r"(a[3]), "r"(b[0]), "r"(b[1]));
}

__device__ __forceinline__ void ldsm_x4(uint32_t& r0, uint32_t& r1, uint32_t& r2,
                                        uint32_t& r3, uint32_t addr) {
    asm volatile("ldmatrix.sync.aligned.m8n8.x4.shared.b16 {%0,%1,%2,%3}, [%4];"
                 : "=r"(r0), "=r"(r1), "=r"(r2), "=r"(r3) : "r"(addr));
}

__device__ __forceinline__ uint32_t smaddr(const void* p) {
    return static_cast<uint32_t>(__cvta_generic_to_shared(p));
}

__device__ __forceinline__ void cp16(uint32_t smem, const void* g) {
    asm volatile("cp.async.cg.shared.global [%0], [%1], 16;" :: "r"(smem), "l"(g) : "memory");
}

// ---------------- merged weight + x pre-pack ----------------
__global__ __launch_bounds__(256) void pack_all_kernel(
    const float* __restrict__ ipW, const float* __restrict__ inW,
    const float* __restrict__ outW, const float* __restrict__ opW,
    const float* __restrict__ xprojW, const float* __restrict__ xin,
    uint32_t* __restrict__ dstHi, uint32_t* __restrict__ dstLo)
{
    int i = blockIdx.x * 256 + threadIdx.x;
    if (i >= WPK_HALF) return;
    float2 v;
    if (i < WPK_XP) {
        const float* src;
        int local;
        if (i < WPK_IN)       { src = ipW;  local = i - WPK_IP; }
        else if (i < WPK_OUT) { src = inW;  local = i - WPK_IN; }
        else if (i < WPK_OP)  { src = outW; local = i - WPK_OUT; }
        else                  { src = opW;  local = i - WPK_OP; }
        v = *reinterpret_cast<const float2*>(&src[2 * local]);
    } else if (i < WPK_XIN) {
        int q = i - WPK_XP;                // [0, 65536)
        int ldir = q >> 14;                // 0..3
        int rem = q & 16383;
        int row = rem >> 8;                // 0..63
        int wp = rem & 255;
        if (row < 48)
            v = *reinterpret_cast<const float2*>(
                &xprojW[((size_t)ldir * 48 + row) * 512 + wp * 2]);
        else
            v = make_float2(0.f, 0.f);
    } else {
        int local = i - WPK_XIN;
        v = *reinterpret_cast<const float2*>(&xin[2 * local]);
    }
    uint32_t h, l;
    split_pair(v.x, v.y, h, l);
    dstHi[i] = h;
    dstLo[i] = l;
}

// ================= bf16-split mma.sync GEMM (BK=32, cp.async 3-stage) ==========
// BM=64 instantiation used throughout. THREADS = 2*BM; warps in (BM/32)m x 2n grid.
template<int BM>
__global__ __launch_bounds__(BM * 2, (BM == 128) ? 3 : 5) void gemm_bf16_kernel(
    const uint32_t* __restrict__ Ahi, const uint32_t* __restrict__ Alo,
    int ldap, long long sAzp,
    const uint32_t* __restrict__ Whi, const uint32_t* __restrict__ Wlo,
    int ldwp, int sWzp,
    float* __restrict__ C, int ldc, long long sCz, int colOffPerZ,
    uint32_t* __restrict__ CpH, uint32_t* __restrict__ CpL, int ldcp,
    const float* __restrict__ bias, int sBiasZ,
    const float* __restrict__ resid, int ldres,
    int N_, int K_, int flags)
{
    constexpr int THREADS = BM * 2;
    constexpr int A_PLANE = BM * 64;
    constexpr int W_OFF   = 2 * A_PLANE;
    constexpr int STAGE   = 2 * A_PLANE + 8192;
    constexpr int AUH     = 2;              // A units per thread per plane
    constexpr int WUH     = 256 / THREADS;  // W units per thread per plane

    extern __shared__ unsigned char gsm[];
    const uint32_t sb = smaddr(gsm);

    const int tid = threadIdx.x;
    const int wid = tid >> 5, lane = tid & 31;
    const int wm = wid >> 1, wn = wid & 1;
    const int r = lane >> 2, c = lane & 3;

    const int z = blockIdx.z;
    const int m0 = blockIdx.y * BM, n0 = blockIdx.x * 64;
    const uint32_t* AhiZ = Ahi + (size_t)z * sAzp;
    const uint32_t* AloZ = Alo + (size_t)z * sAzp;
    const uint32_t* WhiZ = Whi + (size_t)z * sWzp;
    const uint32_t* WloZ = Wlo + (size_t)z * sWzp;

    float4 acc[2][4];
#pragma unroll
    for (int i = 0; i < 2; i++)
#pragma unroll
        for (int j = 0; j < 4; j++) acc[i][j] = make_float4(0.f, 0.f, 0.f, 0.f);

    const int NC = K_ >> 5;

    // cp.async mappings — one entry per plane-pair (hi/lo share row & swizzle)
    uint32_t aSo[AUH]; size_t aG[AUH];
#pragma unroll
    for (int i = 0; i < AUH; i++) {
        int u = tid + i * THREADS;         // < 4*BM
        int row = u >> 2, q = u & 3;
        aSo[i] = (uint32_t)(row * 64 + ((q ^ ((row >> 1) & 3)) * 16));
        aG[i] = (size_t)(m0 + row) * ldap + q * 4;
    }
    uint32_t wSo[WUH]; size_t wG[WUH];
#pragma unroll
    for (int i = 0; i < WUH; i++) {
        int u = tid + i * THREADS;         // < 256
        int row = u >> 2, q = u & 3;
        wSo[i] = (uint32_t)(W_OFF + row * 64 + ((q ^ ((row >> 1) & 3)) * 16));
        wG[i] = (size_t)(n0 + row) * ldwp + q * 4;
    }

#pragma unroll
    for (int pc = 0; pc < STAGES - 1; pc++) {
        const uint32_t so = sb + pc * STAGE;
        const int cw = pc * 16;
#pragma unroll
        for (int i = 0; i < AUH; i++) {
            cp16(so + aSo[i],            AhiZ + aG[i] + cw);
            cp16(so + A_PLANE + aSo[i],  AloZ + aG[i] + cw);
        }
#pragma unroll
        for (int i = 0; i < WUH; i++) {
            cp16(so + wSo[i],        WhiZ + wG[i] + cw);
            cp16(so + 4096 + wSo[i], WloZ + wG[i] + cw);
        }
        asm volatile("cp.async.commit_group;" ::: "memory");
    }

    const int mrow_in = ((lane >> 3) & 1) * 8 + (lane & 7);
    const int aUnitHi = lane >> 4;
    const int bUnitHi = (lane >> 3) & 1;
    const int bNtSel  = lane >> 4;
    const int bRowIn  = lane & 7;

    for (int cc = 0; cc < NC; cc++) {
        asm volatile("cp.async.wait_group 1;" ::: "memory");
        __syncthreads();

        if (cc + STAGES - 1 < NC) {
            const int nc2 = cc + STAGES - 1;
            const uint32_t so = sb + (nc2 % STAGES) * STAGE;
            const int cw = nc2 * 16;
#pragma unroll
            for (int i = 0; i < AUH; i++) {
                cp16(so + aSo[i],            AhiZ + aG[i] + cw);
                cp16(so + A_PLANE + aSo[i],  AloZ + aG[i] + cw);
            }
#pragma unroll
            for (int i = 0; i < WUH; i++) {
                cp16(so + wSo[i],        WhiZ + wG[i] + cw);
                cp16(so + 4096 + wSo[i], WloZ + wG[i] + cw);
            }
        }
        asm volatile("cp.async.commit_group;" ::: "memory");

        const uint32_t a0b = sb + (cc % STAGES) * STAGE;
        const uint32_t a1b = a0b + A_PLANE;
        const uint32_t w0b = a0b + W_OFF;
        const uint32_t w1b = w0b + 4096;
#pragma unroll
        for (int s = 0; s < 2; s++) {
            uint32_t ah[2][4], al[2][4], bh[4][2], bl[4][2];
#pragma unroll
            for (int mt = 0; mt < 2; mt++) {
                int mrow = (wm * 2 + mt) * 16 + mrow_in;
                int q = (2 * s + aUnitHi) ^ ((mrow >> 1) & 3);
                uint32_t off = (uint32_t)(mrow * 64 + q * 16);
                ldsm_x4(ah[mt][0], ah[mt][1], ah[mt][2], ah[mt][3], a0b + off);
                ldsm_x4(al[mt][0], al[mt][1], al[mt][2], al[mt][3], a1b + off);
            }
#pragma unroll
            for (int p = 0; p < 2; p++) {
                int ntile = wn * 4 + p * 2 + bNtSel;
                int nrow = ntile * 8 + bRowIn;
                int q = (2 * s + bUnitHi) ^ ((nrow >> 1) & 3);
                uint32_t off = (uint32_t)(nrow * 64 + q * 16);
                ldsm_x4(bh[p * 2][0], bh[p * 2][1], bh[p * 2 + 1][0], bh[p * 2 + 1][1],
                        w0b + off);
                ldsm_x4(bl[p * 2][0], bl[p * 2][1], bl[p * 2 + 1][0], bl[p * 2 + 1][1],
                        w1b + off);
            }
#pragma unroll
            for (int mt = 0; mt < 2; mt++)
#pragma unroll
                for (int nt = 0; nt < 4; nt++) {
                    mma_bf16(acc[mt][nt], ah[mt], bh[nt]);
                    mma_bf16(acc[mt][nt], al[mt], bh[nt]);
                    mma_bf16(acc[mt][nt], ah[mt], bl[nt]);
                }
        }
    }

    const int coff = colOffPerZ * z;
#pragma unroll
    for (int mt = 0; mt < 2; mt++) {
        int mA = m0 + wm * 32 + mt * 16 + r;
        int mB = mA + 8;
        int rA = mA, rB = mB;
        if ((flags & FLAG_FLIP) && z == 1) {
            rA = (mA & ~(SS - 1)) + ((SS - 1) - (mA & (SS - 1)));
            rB = (mB & ~(SS - 1)) + ((SS - 1) - (mB & (SS - 1)));
        }
#pragma unroll
        for (int nt = 0; nt < 4; nt++) {
            int n = n0 + wn * 32 + nt * 8 + 2 * c;
            if (n >= N_) continue;
            float2 vA = make_float2(acc[mt][nt].x, acc[mt][nt].y);
            float2 vB = make_float2(acc[mt][nt].z, acc[mt][nt].w);
            if (bias) {
                float2 bv = *reinterpret_cast<const float2*>(&bias[z * sBiasZ + n]);
                vA.x += bv.x; vA.y += bv.y;
                vB.x += bv.x; vB.y += bv.y;
            }
            if (resid) {
                float2 qa = *reinterpret_cast<const float2*>(
                    &resid[(size_t)rA * ldres + coff + n]);
                float2 qb = *reinterpret_cast<const float2*>(
                    &resid[(size_t)rB * ldres + coff + n]);
                vA.x += qa.x; vA.y += qa.y;
                vB.x += qb.x; vB.y += qb.y;
            }
            if (flags & FLAG_F32OUT) {
                *reinterpret_cast<float2*>(
                    &C[(size_t)z * sCz + (size_t)rA * ldc + coff + n]) = vA;
                *reinterpret_cast<float2*>(
                    &C[(size_t)z * sCz + (size_t)rB * ldc + coff + n]) = vB;
            }
            if (flags & FLAG_PACKOUT) {
                uint32_t h, l;
                int wI = (coff + n) >> 1;
                split_pair(vA.x, vA.y, h, l);
                CpH[(size_t)rA * ldcp + wI] = h;
                CpL[(size_t)rA * ldcp + wI] = l;
                split_pair(vB.x, vB.y, h, l);
                CpH[(size_t)rB * ldcp + wI] = h;
                CpL[(size_t)rB * ldcp + wI] = l;
            }
        }
    }
}

// ---------------- LayerNorm, warp-per-row (Dvec=256, packed bf16 hi/lo out) ----------
__global__ __launch_bounds__(256) void ln256_kernel(
    const float* __restrict__ src,   // [MM][512]; z reads cols z*256.. (z=1 flipped S)
    const float* __restrict__ g, const float* __restrict__ bta,
    uint32_t* __restrict__ pH, uint32_t* __restrict__ pL)
{
    const int warp = threadIdx.x >> 5, lane = threadIdx.x & 31;
    const int m = blockIdx.x * 8 + warp;
    const int z = blockIdx.y;
    int srow = m;
    if (z == 1)
        srow = (m & ~(SS - 1)) + ((SS - 1) - (m & (SS - 1)));
    const float* sp = src + (size_t)srow * 512 + z * 256;

    float4 va = *reinterpret_cast<const float4*>(&sp[lane * 4]);
    float4 vb = *reinterpret_cast<const float4*>(&sp[128 + lane * 4]);
    float s1 = va.x + va.y + va.z + va.w + vb.x + vb.y + vb.z + vb.w;
    float s2 = va.x * va.x + va.y * va.y + va.z * va.z + va.w * va.w
             + vb.x * vb.x + vb.y * vb.y + vb.z * vb.z + vb.w * vb.w;
#pragma unroll
    for (int o = 16; o > 0; o >>= 1) {
        s1 += __shfl_xor_sync(0xffffffffu, s1, o);
        s2 += __shfl_xor_sync(0xffffffffu, s2, o);
    }
    const float mean = s1 * (1.f / 256.f);
    const float var  = s2 * (1.f / 256.f) - mean * mean;
    const float inv  = rsqrtf(var + 1e-5f);

    const float* gz = g + z * 256;
    const float* bz = bta + z * 256;
    float4 ga = *reinterpret_cast<const float4*>(&gz[lane * 4]);
    float4 gb = *reinterpret_cast<const float4*>(&gz[128 + lane * 4]);
    float4 ba = *reinterpret_cast<const float4*>(&bz[lane * 4]);
    float4 bb = *reinterpret_cast<const float4*>(&bz[128 + lane * 4]);

    float o0 = (va.x - mean) * inv * ga.x + ba.x;
    float o1 = (va.y - mean) * inv * ga.y + ba.y;
    float o2 = (va.z - mean) * inv * ga.z + ba.z;
    float o3 = (va.w - mean) * inv * ga.w + ba.w;
    float o4 = (vb.x - mean) * inv * gb.x + bb.x;
    float o5 = (vb.y - mean) * inv * gb.y + bb.y;
    float o6 = (vb.z - mean) * inv * gb.z + bb.z;
    float o7 = (vb.w - mean) * inv * gb.w + bb.w;

    uint32_t h0, l0, h1, l1, h2, l2, h3, l3;
    split_pair(o0, o1, h0, l0); split_pair(o2, o3, h1, l1);
    split_pair(o4, o5, h2, l2); split_pair(o6, o7, h3, l3);
    size_t wbase = ((size_t)z * MM + m) * 128;
    *reinterpret_cast<uint2*>(&pH[wbase + lane * 2])      = make_uint2(h0, h1);
    *reinterpret_cast<uint2*>(&pL[wbase + lane * 2])      = make_uint2(l0, l1);
    *reinterpret_cast<uint2*>(&pH[wbase + 64 + lane * 2]) = make_uint2(h2, h3);
    *reinterpret_cast<uint2*>(&pL[wbase + 64 + lane * 2]) = make_uint2(l2, l3);
}

// ---------------- LayerNorm, warp-per-row (Dvec=512, f32 out) ----------------
__global__ __launch_bounds__(256) void ln512_kernel(
    const float* __restrict__ src, const float* __restrict__ g,
    const float* __restrict__ bta, float* __restrict__ dst)
{
    const int warp = threadIdx.x >> 5, lane = threadIdx.x & 31;
    const int m = blockIdx.x * 8 + warp;
    const float* sp = src + (size_t)m * 512;

    float4 v[4];
    float s1 = 0.f, s2 = 0.f;
#pragma unroll
    for (int i = 0; i < 4; i++) {
        v[i] = *reinterpret_cast<const float4*>(&sp[i * 128 + lane * 4]);
        s1 += v[i].x + v[i].y + v[i].z + v[i].w;
        s2 += v[i].x * v[i].x + v[i].y * v[i].y + v[i].z * v[i].z + v[i].w * v[i].w;
    }
#pragma unroll
    for (int o = 16; o > 0; o >>= 1) {
        s1 += __shfl_xor_sync(0xffffffffu, s1, o);
        s2 += __shfl_xor_sync(0xffffffffu, s2, o);
    }
    const float mean = s1 * (1.f / 512.f);
    const float var  = s2 * (1.f / 512.f) - mean * mean;
    const float inv  = rsqrtf(var + 1e-5f);

    float* dp = dst + (size_t)m * 512;
#pragma unroll
    for (int i = 0; i < 4; i++) {
        float4 gv = *reinterpret_cast<const float4*>(&g[i * 128 + lane * 4]);
        float4 bv = *reinterpret_cast<const float4*>(&bta[i * 128 + lane * 4]);
        float4 o;
        o.x = (v[i].x - mean) * inv * gv.x + bv.x;
        o.y = (v[i].y - mean) * inv * gv.y + bv.y;
        o.z = (v[i].z - mean) * inv * gv.z + bv.z;
        o.w = (v[i].w - mean) * inv * gv.w + bv.w;
        *reinterpret_cast<float4*>(&dp[i * 128 + lane * 4]) = o;
    }
}

// ---------------- causal depthwise conv (K=4) + SiLU; float2; f32 + packed split ----
__global__ __launch_bounds__(256) void conv_silu_kernel(
    const float* __restrict__ xz,   // [2][MM][1024], cols 0..511 are xc-raw
    const float* __restrict__ cW,   // [2][512][4]
    const float* __restrict__ cB,   // [2][512]
    float* __restrict__ xc,         // [2][MM][512] f32 (for scans)
    uint32_t* __restrict__ xcH, uint32_t* __restrict__ xcL)
{
    int idx = blockIdx.x * 256 + threadIdx.x;      // < 2*MM*256 = 2^20
    int dw  = idx & 255;                           // word index (pair of d)
    int row = (idx >> 8) & (MM - 1);
    int z   = idx >> 19;
    int d2  = dw * 2;
    int s   = row & (SS - 1);
    int bs0 = row - s;

    const float4 w0 = *reinterpret_cast<const float4*>(&cW[((size_t)z * 512 + d2) * 4]);
    const float4 w1 = *reinterpret_cast<const float4*>(&cW[((size_t)z * 512 + d2 + 1) * 4]);
    float2 bv = *reinterpret_cast<const float2*>(&cB[z * 512 + d2]);
    float a0 = bv.x, a1 = bv.y;
    const float* xzz = xz + (size_t)z * MM * 1024;
#pragma unroll
    for (int k = 0; k < 4; k++) {
        int sp = s - 3 + k;
        if (sp >= 0) {
            float2 xv = *reinterpret_cast<const float2*>(
                &xzz[(size_t)(bs0 + sp) * 1024 + d2]);
            a0 = fmaf((&w0.x)[k], xv.x, a0);
            a1 = fmaf((&w1.x)[k], xv.y, a1);
        }
    }
    float o0 = a0 / (1.f + __expf(-a0));
    float o1 = a1 / (1.f + __expf(-a1));
    size_t oi = (size_t)z * MM * 512 + (size_t)row * 512 + d2;
    *reinterpret_cast<float2*>(&xc[oi]) = make_float2(o0, o1);
    uint32_t h, l;
    split_pair(o0, o1, h, l);
    size_t wi = oi >> 1;
    xcH[wi] = h;
    xcL[wi] = l;
}

// ---------------- packed q-power helper: p[i] = (q^(2i+1), q^(2i+2)) ----------------
__device__ __forceinline__ void qpowers2(float q, unsigned long long* p) {
    float q2 = q * q, q4 = q2 * q2, q8 = q4 * q4;
    unsigned long long q2d, q4d, q8d;
    PACK_DUP(q2d, q2); PACK_DUP(q4d, q4); PACK_DUP(q8d, q8);
    PACKF2(p[0], q, q2);
    MUL2(p[1], p[0], q2d);
    MUL2(p[2], p[0], q4d);
    MUL2(p[3], p[1], q4d);
    MUL2(p[4], p[0], q8d);
    MUL2(p[5], p[1], q8d);
    MUL2(p[6], p[2], q8d);
    MUL2(p[7], p[3], q8d);
}

// ---------------- chunked SSM scan (dt fused; f32x2 fast path) ----------------
__global__ __launch_bounds__(256) void scan_phase1(
    const float* __restrict__ xcp, const float* __restrict__ dblp,
    const float* __restrict__ A_log_l,
    const float* __restrict__ dtW_l, const float* __restrict__ dtB_l,
    float* __restrict__ P, float* __restrict__ hend)
{
    const int chunk = blockIdx.x >> 1;
    const int dg    = blockIdx.x & 1;
    const int b     = blockIdx.y, z = blockIdx.z;
    const int d     = dg * 256 + threadIdx.x;

    __shared__ float sIn[TCH][32];   // [t][0:16 dt-raw inputs, 16:32 B]
    const float* dbl_z = dblp + (size_t)z * MM * 48;
    const int base = b * SS + chunk * TCH;
    for (int i = threadIdx.x; i < TCH * 32; i += 256) {
        int t = i >> 5, n = i & 31;
        sIn[t][n] = dbl_z[(size_t)(base + t) * 48 + n];
    }
    __syncthreads();

    float a[NST], wdt[NST];
    const float* al = A_log_l + ((size_t)z * 512 + d) * NST;
    const float* wl = dtW_l + ((size_t)z * 512 + d) * NST;
    bool fast = true;
#pragma unroll
    for (int n = 0; n < NST; n++) {
        a[n] = -expf(al[n]); wdt[n] = wl[n];
        fast = fast && (fabsf(a[n] + (float)(n + 1)) <= 1e-3f * (n + 1));
    }
    const float bdt = dtB_l[z * 512 + d];
    const float* xcz = xcp + (size_t)z * MM * 512;

    size_t ob = ((((size_t)z * 2 + b) * NCH + chunk) * NST) * 512 + d;

    if (fast) {
        unsigned long long wdtp[8], hq[8], Prq[8], one2;
        PACKF2(one2, 1.f, 1.f);
#pragma unroll
        for (int i = 0; i < 8; i++) {
            PACKF2(wdtp[i], wdt[2 * i], wdt[2 * i + 1]);
            hq[i] = 0ULL;
            Prq[i] = one2;
        }
        for (int t = 0; t < TCH; t++) {
            int row = base + t;
            unsigned long long acc2;
            PACKF2(acc2, bdt, 0.f);
#pragma unroll
            for (int i = 0; i < 8; i++) {
                float2 sv = *reinterpret_cast<const float2*>(&sIn[t][2 * i]);
                unsigned long long sp2;
                PACKF2(sp2, sv.x, sv.y);
                FMA2(acc2, wdtp[i], sp2);
            }
            float dlo, dhi;
            UNPACKF2(dlo, dhi, acc2);
            float draw = dlo + dhi;
            float dtv = (draw > 20.f) ? draw : log1pf(__expf(draw));
            float xv  = xcz[(size_t)row * 512 + d];
            float dx  = dtv * xv;
            unsigned long long p[8];
            qpowers2(__expf(-dtv), p);
            unsigned long long dxd;
            PACK_DUP(dxd, dx);
#pragma unroll
            for (int i = 0; i < 8; i++) {
                float2 Bv = *reinterpret_cast<const float2*>(&sIn[t][16 + 2 * i]);
                unsigned long long Bp, db;
                PACKF2(Bp, Bv.x, Bv.y);
                MUL2(db, dxd, Bp);
                FMA2_3(hq[i], p[i], hq[i], db);
                MUL2(Prq[i], Prq[i], p[i]);
            }
        }
#pragma unroll
        for (int i = 0; i < 8; i++) {
            float plo, phi, hlo, hhi;
            UNPACKF2(plo, phi, Prq[i]);
            UNPACKF2(hlo, hhi, hq[i]);
            P[ob + (size_t)(2 * i) * 512]     = plo;
            P[ob + (size_t)(2 * i + 1) * 512] = phi;
            hend[ob + (size_t)(2 * i) * 512]     = hlo;
            hend[ob + (size_t)(2 * i + 1) * 512] = hhi;
        }
    } else {
        float h[NST], Pr[NST];
#pragma unroll
        for (int n = 0; n < NST; n++) { h[n] = 0.f; Pr[n] = 1.f; }
        for (int t = 0; t < TCH; t++) {
            int row = base + t;
            float draw = bdt;
#pragma unroll
            for (int n = 0; n < NST; n++) draw = fmaf(wdt[n], sIn[t][n], draw);
            float dtv = (draw > 20.f) ? draw : log1pf(__expf(draw));
            float xv  = xcz[(size_t)row * 512 + d];
            float dx  = dtv * xv;
#pragma unroll
            for (int n = 0; n < NST; n++) {
                float dA = __expf(dtv * a[n]);
                h[n]  = fmaf(dA, h[n], dx * sIn[t][16 + n]);
                Pr[n] *= dA;
            }
        }
#pragma unroll
        for (int n = 0; n < NST; n++) {
            P[ob + (size_t)n * 512]    = Pr[n];
            hend[ob + (size_t)n * 512] = h[n];
        }
    }
}

__global__ __launch_bounds__(256) void scan_phase2(
    const float* __restrict__ P, const float* __restrict__ hend,
    float* __restrict__ hinit)
{
    int idx = blockIdx.x * 256 + threadIdx.x;   // 0..32767
    int d = idx & 511;
    int n = (idx >> 9) & 15;
    int b = (idx >> 13) & 1;
    int z = idx >> 14;
    size_t base = ((((size_t)z * 2 + b) * NCH) * NST + n) * 512 + d;
    const size_t cs = (size_t)NST * 512;

    float Pv[NCH], He[NCH];
#pragma unroll
    for (int c = 0; c < NCH; c++) {
        Pv[c] = P[base + (size_t)c * cs];
        He[c] = hend[base + (size_t)c * cs];
    }
    float h = 0.f;
#pragma unroll
    for (int c = 0; c < NCH; c++) {
        hinit[base + (size_t)c * cs] = h;
        h = fmaf(Pv[c], h, He[c]);
    }
}

__global__ __launch_bounds__(256) void scan_phase3(
    const float* __restrict__ xcp, const float* __restrict__ dblp,
    const float* __restrict__ A_log_l,
    const float* __restrict__ dtW_l, const float* __restrict__ dtB_l,
    const float* __restrict__ hinit,
    const float* __restrict__ xzp, const float* __restrict__ Dp_l,
    __nv_bfloat16* __restrict__ ygH, __nv_bfloat16* __restrict__ ygL)
{
    const int chunk = blockIdx.x >> 1;
    const int dg    = blockIdx.x & 1;
    const int b     = blockIdx.y, z = blockIdx.z;
    const int d     = dg * 256 + threadIdx.x;

    __shared__ float sIn[TCH][48];   // [t][0:16 dt-in, 16:32 B, 32:48 C]
    const float* dbl_z = dblp + (size_t)z * MM * 48;
    const int base = b * SS + chunk * TCH;
    for (int i = threadIdx.x; i < TCH * 48; i += 256) {
        int t = i / 48, n = i % 48;
        sIn[t][n] = dbl_z[(size_t)(base + t) * 48 + n];
    }
    __syncthreads();

    float a[NST], wdt[NST];
    const float* al = A_log_l + ((size_t)z * 512 + d) * NST;
    const float* wl = dtW_l + ((size_t)z * 512 + d) * NST;
    bool fast = true;
#pragma unroll
    for (int n = 0; n < NST; n++) {
        a[n] = -expf(al[n]); wdt[n] = wl[n];
        fast = fast && (fabsf(a[n] + (float)(n + 1)) <= 1e-3f * (n + 1));
    }
    const float bdt = dtB_l[z * 512 + d];

    const float Dv = Dp_l[z * 512 + d];
    const float* xcz = xcp + (size_t)z * MM * 512;
    const float* xzz = xzp + (size_t)z * MM * 1024;
    size_t ob = ((((size_t)z * 2 + b) * NCH + chunk) * NST) * 512 + d;

    if (fast) {
        unsigned long long wdtp[8], hq[8];
#pragma unroll
        for (int i = 0; i < 8; i++) {
            PACKF2(wdtp[i], wdt[2 * i], wdt[2 * i + 1]);
            float hlo = hinit[ob + (size_t)(2 * i) * 512];
            float hhi = hinit[ob + (size_t)(2 * i + 1) * 512];
            PACKF2(hq[i], hlo, hhi);
        }
        for (int t = 0; t < TCH; t++) {
            int row = base + t;
            unsigned long long acc2;
            PACKF2(acc2, bdt, 0.f);
#pragma unroll
            for (int i = 0; i < 8; i++) {
                float2 sv = *reinterpret_cast<const float2*>(&sIn[t][2 * i]);
                unsigned long long sp2;
                PACKF2(sp2, sv.x, sv.y);
                FMA2(acc2, wdtp[i], sp2);
            }
            float dlo, dhi;
            UNPACKF2(dlo, dhi, acc2);
            float draw = dlo + dhi;
            float dtv = (draw > 20.f) ? draw : log1pf(__expf(draw));
            float xv  = xcz[(size_t)row * 512 + d];
            float dx  = dtv * xv;
            unsigned long long p[8];
            qpowers2(__expf(-dtv), p);
            unsigned long long dxd, yq = 0ULL;
            PACK_DUP(dxd, dx);
#pragma unroll
            for (int i = 0; i < 8; i++) {
                float2 Bv = *reinterpret_cast<const float2*>(&sIn[t][16 + 2 * i]);
                unsigned long long Bp, db;
                PACKF2(Bp, Bv.x, Bv.y);
                MUL2(db, dxd, Bp);
                FMA2_3(hq[i], p[i], hq[i], db);
                float2 Cv = *reinterpret_cast<const float2*>(&sIn[t][32 + 2 * i]);
                unsigned long long Cp;
                PACKF2(Cp, Cv.x, Cv.y);
                FMA2(yq, hq[i], Cp);
            }
            float ylo, yhi;
            UNPACKF2(ylo, yhi, yq);
            float y = ylo + yhi;
            float yfull = fmaf(xv, Dv, y);
            float zv = xzz[(size_t)row * 1024 + 512 + d];
            float sig = 1.f / (1.f + __expf(-zv));
            float o = yfull * zv * sig;
            size_t oi = (size_t)z * MM * 512 + (size_t)row * 512 + d;
            __nv_bfloat16 hb, lb;
            split_scalar(o, hb, lb);
            ygH[oi] = hb; ygL[oi] = lb;
        }
    } else {
        float h[NST];
#pragma unroll
        for (int n = 0; n < NST; n++) h[n] = hinit[ob + (size_t)n * 512];
        for (int t = 0; t < TCH; t++) {
            int row = base + t;
            float draw = bdt;
#pragma unroll
            for (int n = 0; n < NST; n++) draw = fmaf(wdt[n], sIn[t][n], draw);
            float dtv = (draw > 20.f) ? draw : log1pf(__expf(draw));
            float xv  = xcz[(size_t)row * 512 + d];
            float dx  = dtv * xv;
            float y = 0.f;
#pragma unroll
            for (int n = 0; n < NST; n++) {
                float dA = __expf(dtv * a[n]);
                h[n] = fmaf(dA, h[n], dx * sIn[t][16 + n]);
                y = fmaf(h[n], sIn[t][32 + n], y);
            }
            float yfull = fmaf(xv, Dv, y);
            float zv = xzz[(size_t)row * 1024 + 512 + d];
            float sig = 1.f / (1.f + __expf(-zv));
            float o = yfull * zv * sig;
            size_t oi = (size_t)z * MM * 512 + (size_t)row * 512 + d;
            __nv_bfloat16 hb, lb;
            split_scalar(o, hb, lb);
            ygH[oi] = hb; ygL[oi] = lb;
        }
    }
}

// ---------------- host orchestration ----------------
#define SMEM64  (STAGES * (2 * 64 * 64 + 8192))

extern "C" void kernel_launch(void* const* d_in, const int* in_sizes, int n_in,
                              void* d_out, int out_size)
{
    const float* x      = (const float*)d_in[0];
    const float* ln_g   = (const float*)d_in[1];
    const float* ln_b   = (const float*)d_in[2];
    const float* inW    = (const float*)d_in[3];
    const float* convW  = (const float*)d_in[4];
    const float* convB  = (const float*)d_in[5];
    const float* xprojW = (const float*)d_in[6];
    const float* dtW    = (const float*)d_in[7];
    const float* dtB    = (const float*)d_in[8];
    const float* A_log  = (const float*)d_in[9];
    const float* Dp     = (const float*)d_in[10];
    const float* outW   = (const float*)d_in[11];
    const float* ipW    = (const float*)d_in[12];
    const float* ipB    = (const float*)d_in[13];
    const float* opW    = (const float*)d_in[14];
    const float* opB    = (const float*)d_in[15];
    const float* fln_g  = (const float*)d_in[16];
    const float* fln_b  = (const float*)d_in[17];

    static bool attr_set = false;
    if (!attr_set) {
        cudaFuncSetAttribute(gemm_bf16_kernel<64>,
                             cudaFuncAttributeMaxDynamicSharedMemorySize, SMEM64);
        attr_set = true;
    }

    float* scratch = nullptr;
    cudaGetSymbolAddress((void**)&scratch, g_scratch);
    float* xp   = scratch + OFF_XP;
    float* xzb  = scratch + OFF_XZ;
    float* xc   = scratch + OFF_XC;
    float* dbl  = scratch + OFF_DBL;
    float* hbuf[2] = { scratch + OFF_H0, scratch + OFF_H1 };
    float* Pb   = scratch + OFF_P;
    float* heb  = scratch + OFF_HEND;
    float* hib  = scratch + OFF_HINIT;

    uint32_t* xnH = (uint32_t*)(scratch + OFF_PKXN);
    uint32_t* xnL = xnH + PKXN_W;
    uint32_t* xcH = (uint32_t*)(scratch + OFF_PKXC);
    uint32_t* xcL = xcH + PKXC_W;
    uint32_t* ygH = (uint32_t*)(scratch + OFF_PKYG);
    uint32_t* ygL = ygH + PKYG_W;
    uint32_t* ycH = (uint32_t*)(scratch + OFF_PKYC);
    uint32_t* ycL = ycH + PKYC_W;
    uint32_t* hoH = (uint32_t*)(scratch + OFF_PKHO);
    uint32_t* hoL = hoH + PKHO_W;

    uint32_t* wpk = (uint32_t*)(scratch + OFF_WPK);
    uint32_t* wLo = wpk + WPK_HALF;
    uint32_t* ipH = wpk + WPK_IP;  uint32_t* ipL = wLo + WPK_IP;
    uint32_t* inH = wpk + WPK_IN;  uint32_t* inL = wLo + WPK_IN;
    uint32_t* otH = wpk + WPK_OUT; uint32_t* otL = wLo + WPK_OUT;
    uint32_t* opH = wpk + WPK_OP;  uint32_t* opL = wLo + WPK_OP;
    uint32_t* xpH = wpk + WPK_XP;  uint32_t* xpL = wLo + WPK_XP;
    uint32_t* xiH = wpk + WPK_XIN; uint32_t* xiL = wLo + WPK_XIN;

    // ---- pre-split all weights + input x ----
    pack_all_kernel<<<(WPK_HALF + 255) / 256, 256>>>(
        ipW, inW, outW, opW, xprojW, x, wpk, wLo);

    for (int l = 0; l < LNUM; l++) {
        const size_t l2 = (size_t)l * 2;
        const uint32_t* aH = (l == 0) ? xiH : hoH;
        const uint32_t* aL = (l == 0) ? xiL : hoL;

        // xp = hin @ ipW_l^T + ipB_l          (M=2048, N=512, K=512)
        gemm_bf16_kernel<64><<<dim3(8, 32, 1), 128, SMEM64>>>(
            aH, aL, 256, 0,
            ipH + (size_t)l * 131072, ipL + (size_t)l * 131072, 256, 0,
            xp, 512, 0, 0, nullptr, nullptr, 0,
            ipB + l * 512, 0, nullptr, 0, 512, 512, FLAG_F32OUT);

        // per-dir LN over 256 (dir1 reads cols 256.. flipped S) -> packed xn
        ln256_kernel<<<dim3(MM / 8, 2), 256>>>(
            xp, ln_g + l2 * 256, ln_b + l2 * 256, xnH, xnL);

        // xz = xn @ inW^T                      (N=1024, K=256), both dirs
        gemm_bf16_kernel<64><<<dim3(16, 32, 2), 128, SMEM64>>>(
            xnH, xnL, 128, (long long)MM * 128,
            inH + l2 * 131072, inL + l2 * 131072, 128, 131072,
            xzb, 1024, (long long)MM * 1024, 0, nullptr, nullptr, 0,
            nullptr, 0, nullptr, 0, 1024, 256, FLAG_F32OUT);

        // causal dwconv + silu -> f32 xc + packed xc
        conv_silu_kernel<<<(2 * MM * 256) / 256, 256>>>(
            xzb, convW + l2 * 512 * 4, convB + l2 * 512, xc, xcH, xcL);

        // dbl = xc @ xprojW^T                  (N=48 pad 64, K=512)
        gemm_bf16_kernel<64><<<dim3(1, 32, 2), 128, SMEM64>>>(
            xcH, xcL, 256, (long long)MM * 256,
            xpH + l2 * 16384, xpL + l2 * 16384, 256, 16384,
            dbl, 48, (long long)MM * 48, 0, nullptr, nullptr, 0,
            nullptr, 0, nullptr, 0, 48, 512, FLAG_F32OUT);

        // chunked scan (dt fused); phase3 emits packed yg
        scan_phase1<<<dim3(NCH * 2, 2, 2), 256>>>(
            xc, dbl, A_log + l2 * 512 * NST,
            dtW + l2 * 512 * NST, dtB + l2 * 512, Pb, heb);
        scan_phase2<<<128, 256>>>(Pb, heb, hib);
        scan_phase3<<<dim3(NCH * 2, 2, 2), 256>>>(
            xc, dbl, A_log + l2 * 512 * NST,
            dtW + l2 * 512 * NST, dtB + l2 * 512,
            hib, xzb, Dp + l2 * 512,
            (__nv_bfloat16*)ygH, (__nv_bfloat16*)ygL);

        // ycat[:, z*256..] = u + yg @ outW^T   (N=256, K=512), dir1 flip -> packed
        gemm_bf16_kernel<64><<<dim3(4, 32, 2), 128, SMEM64>>>(
            ygH, ygL, 256, (long long)MM * 256,
            otH + l2 * 65536, otL + l2 * 65536, 256, 65536,
            nullptr, 512, 0, 256, ycH, ycL, 256,
            nullptr, 0, xp, 512, 256, 512, FLAG_PACKOUT | FLAG_FLIP);

        // h_next = ycat @ opW^T + opB          (N=512, K=512) -> f32 + packed
        float* hout = hbuf[l & 1];
        gemm_bf16_kernel<64><<<dim3(8, 32, 1), 128, SMEM64>>>(
            ycH, ycL, 256, 0,
            opH + (size_t)l * 131072, opL + (size_t)l * 131072, 256, 0,
            hout, 512, 0, 0, hoH, hoL, 256,
            opB + l * 512, 0, nullptr, 0, 512, 512, FLAG_F32OUT | FLAG_PACKOUT);
    }

    // final LN over 512 -> d_out
    ln512_kernel<<<dim3(MM / 8, 1), 256>>>(
        hbuf[(LNUM - 1) & 1], fln_g, fln_b, (float*)d_out);
}